// round 2
// baseline (speedup 1.0000x reference)
#include <cuda_runtime.h>
#include <cuda_bf16.h>

// Problem constants: B=1, H=8, L=4096, D=64, block 64x64, 16 samples per block.
#define NHEADS 8

__device__ int g_keep_list[NHEADS][64][64];
__device__ int g_keep_count[NHEADS][64];

// ---------------------------------------------------------------------------
// Kernel 1: pooled downsampled attention -> per-(h,qb) kept key-block list.
// Grid (64 qblocks, 8 heads), 256 threads.
// Dynamic smem: SK[256][65] + S[16][1025]  (132160 B)
// ---------------------------------------------------------------------------
__global__ __launch_bounds__(256, 1) void pool_mask_kernel(
    const float* __restrict__ q, const float* __restrict__ k,
    const int* __restrict__ sidq, const int* __restrict__ sidk)
{
    const int qb = blockIdx.x, h = blockIdx.y;
    const int t = threadIdx.x;
    extern __shared__ float dynp[];
    float* SK = dynp;               // 256 x 65 (one 256-col chunk of sampled K)
    float* S  = dynp + 256 * 65;    // 16 x 1025 (full sampled-score matrix)
    __shared__ float SQ[16 * 65];
    __shared__ int sqi[16], ski[16];
    __shared__ float rowinv[16];
    __shared__ float pooled[64];
    __shared__ float ppart[256];
    __shared__ int keepflag[64];
    __shared__ float total_s;

    if (t < 16) { sqi[t] = sidq[h * 16 + t]; ski[t] = sidk[h * 16 + t]; }
    __syncthreads();

    // Load 16 sampled q rows of this q-block (16 rows x 16 float4 = 256 slots).
    {
        int r = t >> 4, c4 = (t & 15) << 2;
        int grow = (qb << 6) + sqi[r];
        float4 val = *reinterpret_cast<const float4*>(q + ((((h << 12) + grow) << 6) + c4));
        SQ[r * 65 + c4 + 0] = val.x; SQ[r * 65 + c4 + 1] = val.y;
        SQ[r * 65 + c4 + 2] = val.z; SQ[r * 65 + c4 + 3] = val.w;
    }

    const int rt = t >> 6;   // 0..3  -> 4 q rows each
    const int ct = t & 63;   // 0..63 -> cols {ct, ct+64, ct+128, ct+192}

    // Score matrix S[16][1024] in 4 chunks of 256 sampled-k columns.
    for (int ck = 0; ck < 4; ck++) {
        __syncthreads();
        for (int i = t; i < 4096; i += 256) {
            int r = i >> 4, c4 = (i & 15) << 2;
            int kb = (ck << 4) + (r >> 4);
            int grow = (kb << 6) + ski[r & 15];
            float4 val = *reinterpret_cast<const float4*>(k + ((((h << 12) + grow) << 6) + c4));
            SK[r * 65 + c4 + 0] = val.x; SK[r * 65 + c4 + 1] = val.y;
            SK[r * 65 + c4 + 2] = val.z; SK[r * 65 + c4 + 3] = val.w;
        }
        __syncthreads();
        float sacc[4][4] = {};
        for (int d = 0; d < 64; d++) {
            float qv[4], kv[4];
            #pragma unroll
            for (int i = 0; i < 4; i++) qv[i] = SQ[((rt << 2) + i) * 65 + d];
            #pragma unroll
            for (int j = 0; j < 4; j++) kv[j] = SK[(ct + (j << 6)) * 65 + d];
            #pragma unroll
            for (int i = 0; i < 4; i++)
                #pragma unroll
                for (int j = 0; j < 4; j++) sacc[i][j] += qv[i] * kv[j];
        }
        #pragma unroll
        for (int i = 0; i < 4; i++)
            #pragma unroll
            for (int j = 0; j < 4; j++)
                S[((rt << 2) + i) * 1025 + (ck << 8) + ct + (j << 6)] = sacc[i][j] * 0.125f;
    }
    __syncthreads();

    // Row softmax (store unnormalized exp back, keep 1/rowsum).
    {
        int w = t >> 5, lane = t & 31;
        for (int rr = 0; rr < 2; rr++) {
            int r = (w << 1) + rr;
            float m = -1e30f;
            for (int c = lane; c < 1024; c += 32) m = fmaxf(m, S[r * 1025 + c]);
            #pragma unroll
            for (int off = 16; off; off >>= 1) m = fmaxf(m, __shfl_xor_sync(0xffffffffu, m, off));
            float sum = 0.f;
            for (int c = lane; c < 1024; c += 32) {
                float p = __expf(S[r * 1025 + c] - m);
                S[r * 1025 + c] = p;
                sum += p;
            }
            #pragma unroll
            for (int off = 16; off; off >>= 1) sum += __shfl_xor_sync(0xffffffffu, sum, off);
            if (lane == 0) rowinv[r] = 1.f / sum;
        }
    }
    __syncthreads();

    // 16x16 sum-pool: pooled[kb] = sum_{r,j} P[r][kb*16+j]
    {
        int kb = t >> 2, part = t & 3;
        float acc = 0.f;
        #pragma unroll
        for (int i = 0; i < 4; i++) {
            int r = (part << 2) + i;
            float s = 0.f;
            #pragma unroll
            for (int j = 0; j < 16; j++) s += S[r * 1025 + (kb << 4) + j];
            acc += s * rowinv[r];
        }
        ppart[t] = acc;
    }
    __syncthreads();
    if (t < 64)
        pooled[t] = ppart[t * 4] + ppart[t * 4 + 1] + ppart[t * 4 + 2] + ppart[t * 4 + 3];
    __syncthreads();
    if (t == 0) { float tot = 0.f; for (int i = 0; i < 64; i++) tot += pooled[i]; total_s = tot; }
    __syncthreads();

    // keep iff cumulative pooled mass of strictly-higher-ranked blocks < 50%.
    // Rank: descending value, ties broken by ascending index (stable argsort of -pooling).
    if (t < 64) {
        float mine = pooled[t], before = 0.f;
        for (int j = 0; j < 64; j++) {
            float pj = pooled[j];
            if (pj > mine || (pj == mine && j < t)) before += pj;
        }
        keepflag[t] = (before < 0.5f * total_s) ? 1 : 0;
    }
    __syncthreads();
    if (t == 0) {
        int cnt = 0;
        for (int b = 0; b < 64; b++)
            if (keepflag[b]) g_keep_list[h][qb][cnt++] = b;
        g_keep_count[h][qb] = cnt;
    }
}

// ---------------------------------------------------------------------------
// Kernel 2: block-sparse flash attention over kept blocks.
// Grid (64 qblocks, 8 heads), 128 threads.
// Thread tiles: S phase 8 rows x 4 strided cols; PV phase 8 rows x 4 strided dims.
// Dynamic smem: Q,K,V,P each 64x65 (66560 B).
// ---------------------------------------------------------------------------
__global__ __launch_bounds__(128, 3) void attn_kernel(
    const float* __restrict__ q, const float* __restrict__ k,
    const float* __restrict__ v, float* __restrict__ out)
{
    const int qb = blockIdx.x, h = blockIdx.y;
    const int t = threadIdx.x;
    extern __shared__ float dyna[];
    float* Qs = dyna;            // 64 x 65
    float* Ks = Qs + 64 * 65;
    float* Vs = Ks + 64 * 65;
    float* Ps = Vs + 64 * 65;
    __shared__ float m_s[64], l_s[64];
    __shared__ int keep_s[64];
    __shared__ int cnt_s;

    if (t == 0) cnt_s = g_keep_count[h][qb];
    if (t < 64) {
        keep_s[t] = g_keep_list[h][qb][t];
        m_s[t] = -1e30f;
        l_s[t] = 0.f;
    }
    for (int i = t; i < 1024; i += 128) {
        int r = i >> 4, c4 = (i & 15) << 2;
        float4 val = *reinterpret_cast<const float4*>(q + ((((h << 12) + (qb << 6) + r) << 6) + c4));
        Qs[r * 65 + c4 + 0] = val.x * 0.125f; Qs[r * 65 + c4 + 1] = val.y * 0.125f;
        Qs[r * 65 + c4 + 2] = val.z * 0.125f; Qs[r * 65 + c4 + 3] = val.w * 0.125f;
    }
    __syncthreads();

    const int tr = t >> 4;   // 0..7  -> rows tr*8 .. tr*8+7
    const int tc = t & 15;   // 0..15 -> cols/dims {tc, tc+16, tc+32, tc+48}
    float acc[8][4] = {};
    const int cnt = cnt_s;

    for (int it = 0; it < cnt; it++) {
        const int kb = keep_s[it];
        const int base = (((h << 12) + (kb << 6)) << 6);
        for (int i = t; i < 1024; i += 128) {
            int r = i >> 4, c4 = (i & 15) << 2;
            float4 kv4 = *reinterpret_cast<const float4*>(k + base + (r << 6) + c4);
            float4 vv4 = *reinterpret_cast<const float4*>(v + base + (r << 6) + c4);
            Ks[r * 65 + c4 + 0] = kv4.x; Ks[r * 65 + c4 + 1] = kv4.y;
            Ks[r * 65 + c4 + 2] = kv4.z; Ks[r * 65 + c4 + 3] = kv4.w;
            Vs[r * 65 + c4 + 0] = vv4.x; Vs[r * 65 + c4 + 1] = vv4.y;
            Vs[r * 65 + c4 + 2] = vv4.z; Vs[r * 65 + c4 + 3] = vv4.w;
        }
        __syncthreads();

        // S = Q K^T for this 64x64 block (already scaled by 1/8 via Q).
        float sacc[8][4] = {};
        #pragma unroll 8
        for (int d = 0; d < 64; d++) {
            float qv[8], kv[4];
            #pragma unroll
            for (int i = 0; i < 8; i++) qv[i] = Qs[((tr << 3) + i) * 65 + d];
            #pragma unroll
            for (int j = 0; j < 4; j++) kv[j] = Ks[(tc + (j << 4)) * 65 + d];
            #pragma unroll
            for (int i = 0; i < 8; i++)
                #pragma unroll
                for (int j = 0; j < 4; j++) sacc[i][j] += qv[i] * kv[j];
        }

        // Online softmax per row; row r owned by the 16 lanes sharing tr (same warp half).
        #pragma unroll
        for (int i = 0; i < 8; i++) {
            const int r = (tr << 3) + i;
            float mx = fmaxf(fmaxf(sacc[i][0], sacc[i][1]), fmaxf(sacc[i][2], sacc[i][3]));
            #pragma unroll
            for (int off = 8; off; off >>= 1) mx = fmaxf(mx, __shfl_xor_sync(0xffffffffu, mx, off, 16));
            const float mold = m_s[r];
            const float mnew = fmaxf(mold, mx);
            float p0 = __expf(sacc[i][0] - mnew);
            float p1 = __expf(sacc[i][1] - mnew);
            float p2 = __expf(sacc[i][2] - mnew);
            float p3 = __expf(sacc[i][3] - mnew);
            float rs = p0 + p1 + p2 + p3;
            #pragma unroll
            for (int off = 8; off; off >>= 1) rs += __shfl_xor_sync(0xffffffffu, rs, off, 16);
            Ps[r * 65 + tc +  0] = p0;
            Ps[r * 65 + tc + 16] = p1;
            Ps[r * 65 + tc + 32] = p2;
            Ps[r * 65 + tc + 48] = p3;
            const float alpha = __expf(mold - mnew);
            if (tc == 0) { m_s[r] = mnew; l_s[r] = l_s[r] * alpha + rs; }
            #pragma unroll
            for (int j = 0; j < 4; j++) acc[i][j] *= alpha;
        }
        __syncthreads();

        // acc += P @ V
        #pragma unroll 4
        for (int j = 0; j < 64; j++) {
            float pv[8], vv[4];
            #pragma unroll
            for (int i = 0; i < 8; i++) pv[i] = Ps[((tr << 3) + i) * 65 + j];
            #pragma unroll
            for (int jj = 0; jj < 4; jj++) vv[jj] = Vs[j * 65 + tc + (jj << 4)];
            #pragma unroll
            for (int i = 0; i < 8; i++)
                #pragma unroll
                for (int jj = 0; jj < 4; jj++) acc[i][jj] += pv[i] * vv[jj];
        }
        __syncthreads();
    }

    #pragma unroll
    for (int i = 0; i < 8; i++) {
        const int r = (tr << 3) + i;
        const float inv = 1.f / l_s[r];
        const int gbase = (((h << 12) + (qb << 6) + r) << 6);
        #pragma unroll
        for (int j = 0; j < 4; j++) out[gbase + tc + (j << 4)] = acc[i][j] * inv;
    }
}

extern "C" void kernel_launch(void* const* d_in, const int* in_sizes, int n_in,
                              void* d_out, int out_size) {
    const float* q  = (const float*)d_in[0];
    const float* k  = (const float*)d_in[1];
    const float* v  = (const float*)d_in[2];
    const int* siq  = (const int*)d_in[3];
    const int* sik  = (const int*)d_in[4];
    float* out = (float*)d_out;

    const int pool_smem = (256 * 65 + 16 * 1025) * (int)sizeof(float);  // 132160
    const int attn_smem = 4 * 64 * 65 * (int)sizeof(float);             // 66560
    cudaFuncSetAttribute(pool_mask_kernel, cudaFuncAttributeMaxDynamicSharedMemorySize, pool_smem);
    cudaFuncSetAttribute(attn_kernel, cudaFuncAttributeMaxDynamicSharedMemorySize, attn_smem);

    dim3 grid(64, 8);
    pool_mask_kernel<<<grid, 256, pool_smem>>>(q, k, siq, sik);
    attn_kernel<<<grid, 128, attn_smem>>>(q, k, v, out);
}

// round 4
// speedup vs baseline: 1.5620x; 1.5620x over previous
#include <cuda_runtime.h>
#include <cuda_bf16.h>
#include <cstdint>

#define NHEADS 8
__device__ unsigned long long g_keep_bits[NHEADS][64];

// ---------------- helpers ----------------
__device__ __forceinline__ uint32_t smem_u32(const void* p) {
    uint32_t a;
    asm("{ .reg .u64 t; cvta.to.shared.u64 t, %1; cvt.u32.u64 %0, t; }" : "=r"(a) : "l"(p));
    return a;
}
__device__ __forceinline__ void ldm_x4(uint32_t* d, uint32_t addr) {
    asm volatile("ldmatrix.sync.aligned.m8n8.x4.shared.b16 {%0,%1,%2,%3}, [%4];"
                 : "=r"(d[0]), "=r"(d[1]), "=r"(d[2]), "=r"(d[3]) : "r"(addr));
}
__device__ __forceinline__ void ldm_x4_t(uint32_t* d, uint32_t addr) {
    asm volatile("ldmatrix.sync.aligned.m8n8.x4.trans.shared.b16 {%0,%1,%2,%3}, [%4];"
                 : "=r"(d[0]), "=r"(d[1]), "=r"(d[2]), "=r"(d[3]) : "r"(addr));
}
__device__ __forceinline__ void mma16816(float* c, const uint32_t* a, uint32_t b0, uint32_t b1) {
    asm volatile(
        "mma.sync.aligned.m16n8k16.row.col.f32.bf16.bf16.f32 "
        "{%0,%1,%2,%3}, {%4,%5,%6,%7}, {%8,%9}, {%0,%1,%2,%3};"
        : "+f"(c[0]), "+f"(c[1]), "+f"(c[2]), "+f"(c[3])
        : "r"(a[0]), "r"(a[1]), "r"(a[2]), "r"(a[3]), "r"(b0), "r"(b1));
}
// hi/lo bf16 split of two floats -> packed bf16x2 (first arg in low half).
__device__ __forceinline__ void split2(float a, float b, uint32_t& h, uint32_t& l) {
    __nv_bfloat16 ha = __float2bfloat16(a), hb = __float2bfloat16(b);
    __nv_bfloat16 la = __float2bfloat16(a - __bfloat162float(ha));
    __nv_bfloat16 lb = __float2bfloat16(b - __bfloat162float(hb));
    h = (uint32_t)__bfloat16_as_ushort(ha) | ((uint32_t)__bfloat16_as_ushort(hb) << 16);
    l = (uint32_t)__bfloat16_as_ushort(la) | ((uint32_t)__bfloat16_as_ushort(lb) << 16);
}

// ---------------------------------------------------------------------------
// Kernel 1: pooled downsampled attention -> per-(h,qb) keep bitmap. (R1 math.)
// ---------------------------------------------------------------------------
__global__ __launch_bounds__(256, 1) void pool_mask_kernel(
    const float* __restrict__ q, const float* __restrict__ k,
    const int* __restrict__ sidq, const int* __restrict__ sidk)
{
    const int qb = blockIdx.x, h = blockIdx.y;
    const int t = threadIdx.x;
    extern __shared__ float dynp[];
    float* SK = dynp;
    float* S  = dynp + 256 * 65;
    __shared__ float SQ[16 * 65];
    __shared__ int sqi[16], ski[16];
    __shared__ float rowinv[16];
    __shared__ float pooled[64];
    __shared__ float ppart[256];
    __shared__ int keepflag[64];
    __shared__ float total_s;

    if (t < 16) { sqi[t] = sidq[h * 16 + t]; ski[t] = sidk[h * 16 + t]; }
    __syncthreads();
    {
        int r = t >> 4, c4 = (t & 15) << 2;
        int grow = (qb << 6) + sqi[r];
        float4 val = *reinterpret_cast<const float4*>(q + ((((h << 12) + grow) << 6) + c4));
        SQ[r * 65 + c4 + 0] = val.x; SQ[r * 65 + c4 + 1] = val.y;
        SQ[r * 65 + c4 + 2] = val.z; SQ[r * 65 + c4 + 3] = val.w;
    }
    const int rt = t >> 6, ct = t & 63;
    for (int ck = 0; ck < 4; ck++) {
        __syncthreads();
        for (int i = t; i < 4096; i += 256) {
            int r = i >> 4, c4 = (i & 15) << 2;
            int kb = (ck << 4) + (r >> 4);
            int grow = (kb << 6) + ski[r & 15];
            float4 val = *reinterpret_cast<const float4*>(k + ((((h << 12) + grow) << 6) + c4));
            SK[r * 65 + c4 + 0] = val.x; SK[r * 65 + c4 + 1] = val.y;
            SK[r * 65 + c4 + 2] = val.z; SK[r * 65 + c4 + 3] = val.w;
        }
        __syncthreads();
        float sacc[4][4] = {};
        for (int d = 0; d < 64; d++) {
            float qv[4], kv[4];
            #pragma unroll
            for (int i = 0; i < 4; i++) qv[i] = SQ[((rt << 2) + i) * 65 + d];
            #pragma unroll
            for (int j = 0; j < 4; j++) kv[j] = SK[(ct + (j << 6)) * 65 + d];
            #pragma unroll
            for (int i = 0; i < 4; i++)
                #pragma unroll
                for (int j = 0; j < 4; j++) sacc[i][j] += qv[i] * kv[j];
        }
        #pragma unroll
        for (int i = 0; i < 4; i++)
            #pragma unroll
            for (int j = 0; j < 4; j++)
                S[((rt << 2) + i) * 1025 + (ck << 8) + ct + (j << 6)] = sacc[i][j] * 0.125f;
    }
    __syncthreads();
    {
        int w = t >> 5, lane = t & 31;
        for (int rr = 0; rr < 2; rr++) {
            int r = (w << 1) + rr;
            float m = -1e30f;
            for (int c = lane; c < 1024; c += 32) m = fmaxf(m, S[r * 1025 + c]);
            #pragma unroll
            for (int off = 16; off; off >>= 1) m = fmaxf(m, __shfl_xor_sync(0xffffffffu, m, off));
            float sum = 0.f;
            for (int c = lane; c < 1024; c += 32) {
                float p = __expf(S[r * 1025 + c] - m);
                S[r * 1025 + c] = p; sum += p;
            }
            #pragma unroll
            for (int off = 16; off; off >>= 1) sum += __shfl_xor_sync(0xffffffffu, sum, off);
            if (lane == 0) rowinv[r] = 1.f / sum;
        }
    }
    __syncthreads();
    {
        int kb = t >> 2, part = t & 3;
        float acc = 0.f;
        #pragma unroll
        for (int i = 0; i < 4; i++) {
            int r = (part << 2) + i;
            float s = 0.f;
            #pragma unroll
            for (int j = 0; j < 16; j++) s += S[r * 1025 + (kb << 4) + j];
            acc += s * rowinv[r];
        }
        ppart[t] = acc;
    }
    __syncthreads();
    if (t < 64)
        pooled[t] = ppart[t * 4] + ppart[t * 4 + 1] + ppart[t * 4 + 2] + ppart[t * 4 + 3];
    __syncthreads();
    if (t == 0) { float tot = 0.f; for (int i = 0; i < 64; i++) tot += pooled[i]; total_s = tot; }
    __syncthreads();
    if (t < 64) {
        float mine = pooled[t], before = 0.f;
        for (int j = 0; j < 64; j++) {
            float pj = pooled[j];
            if (pj > mine || (pj == mine && j < t)) before += pj;
        }
        keepflag[t] = (before < 0.5f * total_s) ? 1 : 0;
    }
    __syncthreads();
    if (t == 0) {
        unsigned long long bits = 0ull;
        for (int b = 0; b < 64; b++) if (keepflag[b]) bits |= (1ull << b);
        g_keep_bits[h][qb] = bits;
    }
}

// ---------------------------------------------------------------------------
// Kernel 2: block-sparse attention via mma.sync bf16-split HMMA.
// Grid (64 qblocks, 8 heads), 128 threads = 4 warps, warp w owns rows 16w..16w+15.
// No online rescale (scores bounded): O accumulates in C-fragments, l in regs.
// smem tiles bf16 [64][72]: Qhi Qlo Khi Klo Vhi Vlo.
// ---------------------------------------------------------------------------
#define TS 72  // bf16 row stride (144B: 16B-aligned rows, ldmatrix conflict-free)

__global__ __launch_bounds__(128) void attn_hmma_kernel(
    const float* __restrict__ q, const float* __restrict__ k,
    const float* __restrict__ v, float* __restrict__ out)
{
    const int qb = blockIdx.x, h = blockIdx.y;
    const int t = threadIdx.x, w = t >> 5, lane = t & 31;

    extern __shared__ __nv_bfloat16 sm[];
    __nv_bfloat16* Qhi = sm;
    __nv_bfloat16* Qlo = sm + 4608;
    __nv_bfloat16* Khi = sm + 9216;
    __nv_bfloat16* Klo = sm + 13824;
    __nv_bfloat16* Vhi = sm + 18432;
    __nv_bfloat16* Vlo = sm + 23040;
    __shared__ int ulist[64];
    __shared__ int ucnt_s;

    if (t == 0) {
        unsigned long long u = g_keep_bits[h][qb];
        int c = 0;
        for (int b = 0; b < 64; b++) if ((u >> b) & 1ull) ulist[c++] = b;
        ucnt_s = c;
    }

    // Load Q (scale 1/8 folded), hi/lo split. Thread: row t>>1, col half (t&1)*32.
    const int r2 = t >> 1, chalf = (t & 1) * 32;
    {
        const float4* qp4 = (const float4*)(q + ((((h << 12) + (qb << 6) + r2) << 6) + chalf));
        #pragma unroll
        for (int g = 0; g < 4; g++) {
            float4 a = qp4[2 * g], b = qp4[2 * g + 1];
            uint32_t hw[4], lw[4];
            split2(a.x * 0.125f, a.y * 0.125f, hw[0], lw[0]);
            split2(a.z * 0.125f, a.w * 0.125f, hw[1], lw[1]);
            split2(b.x * 0.125f, b.y * 0.125f, hw[2], lw[2]);
            split2(b.z * 0.125f, b.w * 0.125f, hw[3], lw[3]);
            *(uint4*)(Qhi + r2 * TS + chalf + g * 8) = make_uint4(hw[0], hw[1], hw[2], hw[3]);
            *(uint4*)(Qlo + r2 * TS + chalf + g * 8) = make_uint4(lw[0], lw[1], lw[2], lw[3]);
        }
    }
    __syncthreads();

    // Q fragments (persistent): [ks=0..3] x4 regs, hi and lo.
    const int m0 = w * 16;
    uint32_t qfh[4][4], qfl[4][4];
    {
        const int mat = lane >> 3, mr = lane & 7;
        const int arow = m0 + ((mat & 1) << 3) + mr;
        const int acol0 = (mat >> 1) << 3;
        #pragma unroll
        for (int ks = 0; ks < 4; ks++) {
            ldm_x4(qfh[ks], smem_u32(Qhi + arow * TS + 16 * ks + acol0));
            ldm_x4(qfl[ks], smem_u32(Qlo + arow * TS + 16 * ks + acol0));
        }
    }

    float oAcc[8][4] = {};       // O C-fragments, 8 n-tiles of d
    float lsum0 = 0.f, lsum1 = 0.f;
    const int ucnt = ucnt_s;

    // ldmatrix lane addressing pieces
    const int g8 = (lane >> 3) << 3;   // 0,8,16,24
    const int lr = lane & 7;

    for (int it = 0; it < ucnt; it++) {
        const int kb = ulist[it];
        __syncthreads();   // previous iter's V reads done before overwrite
        // K,V tiles hi/lo split. Thread: row r2, cols chalf..chalf+31.
        {
            const int gbase = (((h << 12) + (kb << 6) + r2) << 6) + chalf;
            const float4* kp4 = (const float4*)(k + gbase);
            const float4* vp4 = (const float4*)(v + gbase);
            #pragma unroll
            for (int g = 0; g < 4; g++) {
                float4 a = kp4[2 * g], b = kp4[2 * g + 1];
                uint32_t hw[4], lw[4];
                split2(a.x, a.y, hw[0], lw[0]); split2(a.z, a.w, hw[1], lw[1]);
                split2(b.x, b.y, hw[2], lw[2]); split2(b.z, b.w, hw[3], lw[3]);
                *(uint4*)(Khi + r2 * TS + chalf + g * 8) = make_uint4(hw[0], hw[1], hw[2], hw[3]);
                *(uint4*)(Klo + r2 * TS + chalf + g * 8) = make_uint4(lw[0], lw[1], lw[2], lw[3]);
                a = vp4[2 * g]; b = vp4[2 * g + 1];
                split2(a.x, a.y, hw[0], lw[0]); split2(a.z, a.w, hw[1], lw[1]);
                split2(b.x, b.y, hw[2], lw[2]); split2(b.z, b.w, hw[3], lw[3]);
                *(uint4*)(Vhi + r2 * TS + chalf + g * 8) = make_uint4(hw[0], hw[1], hw[2], hw[3]);
                *(uint4*)(Vlo + r2 * TS + chalf + g * 8) = make_uint4(lw[0], lw[1], lw[2], lw[3]);
            }
        }
        __syncthreads();

        // ---- S = Q K^T (3-term split). C-frags sC[8 n-tiles][4].
        float sC[8][4] = {};
        #pragma unroll
        for (int kk = 0; kk < 2; kk++) {       // k pairs: ks = 2kk, 2kk+1
            #pragma unroll
            for (int nt = 0; nt < 8; nt++) {
                // B mats: rows n0+lr, cols 32kk + g8 (+0/8/16/24)
                uint32_t baddr = (uint32_t)((8 * nt + lr) * TS + 32 * kk + g8) * 2;
                uint32_t bh[4], bl[4];
                ldm_x4(bh, smem_u32(Khi) + baddr);
                ldm_x4(bl, smem_u32(Klo) + baddr);
                mma16816(sC[nt], qfh[2 * kk],     bh[0], bh[1]);
                mma16816(sC[nt], qfh[2 * kk + 1], bh[2], bh[3]);
                mma16816(sC[nt], qfh[2 * kk],     bl[0], bl[1]);
                mma16816(sC[nt], qfh[2 * kk + 1], bl[2], bl[3]);
                mma16816(sC[nt], qfl[2 * kk],     bh[0], bh[1]);
                mma16816(sC[nt], qfl[2 * kk + 1], bh[2], bh[3]);
            }
        }

        // ---- exp, accumulate l, pack P fragments (register-resident).
        uint32_t ph[8][2], pl[8][2];
        #pragma unroll
        for (int nt = 0; nt < 8; nt++) {
            float p0 = __expf(sC[nt][0]), p1 = __expf(sC[nt][1]);
            float p2 = __expf(sC[nt][2]), p3 = __expf(sC[nt][3]);
            lsum0 += p0 + p1; lsum1 += p2 + p3;
            split2(p0, p1, ph[nt][0], pl[nt][0]);
            split2(p2, p3, ph[nt][1], pl[nt][1]);
        }

        // ---- O += P V (3-term split). A-frag for ks: tiles 2ks, 2ks+1.
        #pragma unroll
        for (int kk = 0; kk < 2; kk++) {
            uint32_t pa0[4] = { ph[4*kk][0], ph[4*kk][1], ph[4*kk+1][0], ph[4*kk+1][1] };
            uint32_t la0[4] = { pl[4*kk][0], pl[4*kk][1], pl[4*kk+1][0], pl[4*kk+1][1] };
            uint32_t pa1[4] = { ph[4*kk+2][0], ph[4*kk+2][1], ph[4*kk+3][0], ph[4*kk+3][1] };
            uint32_t la1[4] = { pl[4*kk+2][0], pl[4*kk+2][1], pl[4*kk+3][0], pl[4*kk+3][1] };
            #pragma unroll
            for (int nt = 0; nt < 8; nt++) {
                // V^T B mats via trans: rows kpos 32kk+g8+lr, col d0=8nt
                uint32_t baddr = (uint32_t)((32 * kk + g8 + lr) * TS + 8 * nt) * 2;
                uint32_t bh[4], bl[4];
                ldm_x4_t(bh, smem_u32(Vhi) + baddr);
                ldm_x4_t(bl, smem_u32(Vlo) + baddr);
                mma16816(oAcc[nt], pa0, bh[0], bh[1]);
                mma16816(oAcc[nt], pa1, bh[2], bh[3]);
                mma16816(oAcc[nt], pa0, bl[0], bl[1]);
                mma16816(oAcc[nt], pa1, bl[2], bl[3]);
                mma16816(oAcc[nt], la0, bh[0], bh[1]);
                mma16816(oAcc[nt], la1, bh[2], bh[3]);
            }
        }
    }

    // Reduce l across the quad (width-4 groups share a row).
    #pragma unroll
    for (int off = 1; off < 4; off <<= 1) {
        lsum0 += __shfl_xor_sync(0xffffffffu, lsum0, off, 4);
        lsum1 += __shfl_xor_sync(0xffffffffu, lsum1, off, 4);
    }
    const float inv0 = 1.f / lsum0, inv1 = 1.f / lsum1;

    // Store O: rows m0+lane/4 (+8), cols 8nt+2*(lane%4).
    {
        const int r0 = (qb << 6) + m0 + (lane >> 2);
        const int cc = (lane & 3) << 1;
        float* o0 = out + (((h << 12) + r0) << 6) + cc;
        float* o1 = o0 + (8 << 6);
        #pragma unroll
        for (int nt = 0; nt < 8; nt++) {
            *(float2*)(o0 + 8 * nt) = make_float2(oAcc[nt][0] * inv0, oAcc[nt][1] * inv0);
            *(float2*)(o1 + 8 * nt) = make_float2(oAcc[nt][2] * inv1, oAcc[nt][3] * inv1);
        }
    }
}

extern "C" void kernel_launch(void* const* d_in, const int* in_sizes, int n_in,
                              void* d_out, int out_size) {
    const float* q  = (const float*)d_in[0];
    const float* k  = (const float*)d_in[1];
    const float* v  = (const float*)d_in[2];
    const int* siq  = (const int*)d_in[3];
    const int* sik  = (const int*)d_in[4];
    float* out = (float*)d_out;

    const int pool_smem = (256 * 65 + 16 * 1025) * (int)sizeof(float);  // 132160
    const int attn_smem = 6 * 64 * TS * 2;                               // 55296
    cudaFuncSetAttribute(pool_mask_kernel, cudaFuncAttributeMaxDynamicSharedMemorySize, pool_smem);
    cudaFuncSetAttribute(attn_hmma_kernel, cudaFuncAttributeMaxDynamicSharedMemorySize, attn_smem);

    pool_mask_kernel<<<dim3(64, 8), 256, pool_smem>>>(q, k, siq, sik);
    attn_hmma_kernel<<<dim3(64, 8), 128, attn_smem>>>(q, k, v, out);
}

// round 6
// speedup vs baseline: 1.9678x; 1.2598x over previous
#include <cuda_runtime.h>
#include <cuda_bf16.h>
#include <cstdint>

#define NHEADS 8
#define NELEM 2097152   // 8*4096*64
__device__ unsigned long long g_keep_bits[NHEADS][64];
__device__ __align__(128) __nv_bfloat16 gQhi[NELEM], gQlo[NELEM];
__device__ __align__(128) __nv_bfloat16 gKhi[NELEM], gKlo[NELEM];
__device__ __align__(128) __nv_bfloat16 gVhi[NELEM], gVlo[NELEM];

// ---------------- helpers ----------------
__device__ __forceinline__ uint32_t smem_u32(const void* p) {
    uint32_t a;
    asm("{ .reg .u64 t; cvta.to.shared.u64 t, %1; cvt.u32.u64 %0, t; }" : "=r"(a) : "l"(p));
    return a;
}
__device__ __forceinline__ void ldm_x4(uint32_t* d, uint32_t addr) {
    asm volatile("ldmatrix.sync.aligned.m8n8.x4.shared.b16 {%0,%1,%2,%3}, [%4];"
                 : "=r"(d[0]), "=r"(d[1]), "=r"(d[2]), "=r"(d[3]) : "r"(addr));
}
__device__ __forceinline__ void ldm_x4_t(uint32_t* d, uint32_t addr) {
    asm volatile("ldmatrix.sync.aligned.m8n8.x4.trans.shared.b16 {%0,%1,%2,%3}, [%4];"
                 : "=r"(d[0]), "=r"(d[1]), "=r"(d[2]), "=r"(d[3]) : "r"(addr));
}
__device__ __forceinline__ void mma16816(float* c, const uint32_t* a, uint32_t b0, uint32_t b1) {
    asm volatile(
        "mma.sync.aligned.m16n8k16.row.col.f32.bf16.bf16.f32 "
        "{%0,%1,%2,%3}, {%4,%5,%6,%7}, {%8,%9}, {%0,%1,%2,%3};"
        : "+f"(c[0]), "+f"(c[1]), "+f"(c[2]), "+f"(c[3])
        : "r"(a[0]), "r"(a[1]), "r"(a[2]), "r"(a[3]), "r"(b0), "r"(b1));
}
__device__ __forceinline__ void split2(float a, float b, uint32_t& h, uint32_t& l) {
    __nv_bfloat16 ha = __float2bfloat16(a), hb = __float2bfloat16(b);
    __nv_bfloat16 la = __float2bfloat16(a - __bfloat162float(ha));
    __nv_bfloat16 lb = __float2bfloat16(b - __bfloat162float(hb));
    h = (uint32_t)__bfloat16_as_ushort(ha) | ((uint32_t)__bfloat16_as_ushort(hb) << 16);
    l = (uint32_t)__bfloat16_as_ushort(la) | ((uint32_t)__bfloat16_as_ushort(lb) << 16);
}
__device__ __forceinline__ void cp16(uint32_t dst, const void* src) {
    asm volatile("cp.async.cg.shared.global [%0], [%1], 16;" :: "r"(dst), "l"(src));
}
#define CP_COMMIT() asm volatile("cp.async.commit_group;" ::: "memory")
#define CP_WAIT1()  asm volatile("cp.async.wait_group 1;" ::: "memory")

// ---------------------------------------------------------------------------
// Kernel 0: split Q (x1/8), K, V into hi/lo bf16 global arrays.
// ---------------------------------------------------------------------------
__global__ __launch_bounds__(256) void split_prepass(
    const float* __restrict__ q, const float* __restrict__ k, const float* __restrict__ v)
{
    const int idx = (blockIdx.x * 256 + threadIdx.x) * 8;
    float4 a, b; uint32_t hw[4], lw[4];

    a = *(const float4*)(q + idx); b = *(const float4*)(q + idx + 4);
    split2(a.x * 0.125f, a.y * 0.125f, hw[0], lw[0]);
    split2(a.z * 0.125f, a.w * 0.125f, hw[1], lw[1]);
    split2(b.x * 0.125f, b.y * 0.125f, hw[2], lw[2]);
    split2(b.z * 0.125f, b.w * 0.125f, hw[3], lw[3]);
    *(uint4*)(gQhi + idx) = make_uint4(hw[0], hw[1], hw[2], hw[3]);
    *(uint4*)(gQlo + idx) = make_uint4(lw[0], lw[1], lw[2], lw[3]);

    a = *(const float4*)(k + idx); b = *(const float4*)(k + idx + 4);
    split2(a.x, a.y, hw[0], lw[0]); split2(a.z, a.w, hw[1], lw[1]);
    split2(b.x, b.y, hw[2], lw[2]); split2(b.z, b.w, hw[3], lw[3]);
    *(uint4*)(gKhi + idx) = make_uint4(hw[0], hw[1], hw[2], hw[3]);
    *(uint4*)(gKlo + idx) = make_uint4(lw[0], lw[1], lw[2], lw[3]);

    a = *(const float4*)(v + idx); b = *(const float4*)(v + idx + 4);
    split2(a.x, a.y, hw[0], lw[0]); split2(a.z, a.w, hw[1], lw[1]);
    split2(b.x, b.y, hw[2], lw[2]); split2(b.z, b.w, hw[3], lw[3]);
    *(uint4*)(gVhi + idx) = make_uint4(hw[0], hw[1], hw[2], hw[3]);
    *(uint4*)(gVlo + idx) = make_uint4(lw[0], lw[1], lw[2], lw[3]);
}

// ---------------------------------------------------------------------------
// Kernel 1: pooled downsampled attention -> keep bitmap. (Unchanged, passing.)
// ---------------------------------------------------------------------------
__global__ __launch_bounds__(256, 1) void pool_mask_kernel(
    const float* __restrict__ q, const float* __restrict__ k,
    const int* __restrict__ sidq, const int* __restrict__ sidk)
{
    const int qb = blockIdx.x, h = blockIdx.y;
    const int t = threadIdx.x;
    extern __shared__ float dynp[];
    float* SK = dynp;
    float* S  = dynp + 256 * 65;
    __shared__ float SQ[16 * 65];
    __shared__ int sqi[16], ski[16];
    __shared__ float rowinv[16];
    __shared__ float pooled[64];
    __shared__ float ppart[256];
    __shared__ int keepflag[64];
    __shared__ float total_s;

    if (t < 16) { sqi[t] = sidq[h * 16 + t]; ski[t] = sidk[h * 16 + t]; }
    __syncthreads();
    {
        int r = t >> 4, c4 = (t & 15) << 2;
        int grow = (qb << 6) + sqi[r];
        float4 val = *reinterpret_cast<const float4*>(q + ((((h << 12) + grow) << 6) + c4));
        SQ[r * 65 + c4 + 0] = val.x; SQ[r * 65 + c4 + 1] = val.y;
        SQ[r * 65 + c4 + 2] = val.z; SQ[r * 65 + c4 + 3] = val.w;
    }
    const int rt = t >> 6, ct = t & 63;
    for (int ck = 0; ck < 4; ck++) {
        __syncthreads();
        for (int i = t; i < 4096; i += 256) {
            int r = i >> 4, c4 = (i & 15) << 2;
            int kb = (ck << 4) + (r >> 4);
            int grow = (kb << 6) + ski[r & 15];
            float4 val = *reinterpret_cast<const float4*>(k + ((((h << 12) + grow) << 6) + c4));
            SK[r * 65 + c4 + 0] = val.x; SK[r * 65 + c4 + 1] = val.y;
            SK[r * 65 + c4 + 2] = val.z; SK[r * 65 + c4 + 3] = val.w;
        }
        __syncthreads();
        float sacc[4][4] = {};
        for (int d = 0; d < 64; d++) {
            float qv[4], kv[4];
            #pragma unroll
            for (int i = 0; i < 4; i++) qv[i] = SQ[((rt << 2) + i) * 65 + d];
            #pragma unroll
            for (int j = 0; j < 4; j++) kv[j] = SK[(ct + (j << 6)) * 65 + d];
            #pragma unroll
            for (int i = 0; i < 4; i++)
                #pragma unroll
                for (int j = 0; j < 4; j++) sacc[i][j] += qv[i] * kv[j];
        }
        #pragma unroll
        for (int i = 0; i < 4; i++)
            #pragma unroll
            for (int j = 0; j < 4; j++)
                S[((rt << 2) + i) * 1025 + (ck << 8) + ct + (j << 6)] = sacc[i][j] * 0.125f;
    }
    __syncthreads();
    {
        int w = t >> 5, lane = t & 31;
        for (int rr = 0; rr < 2; rr++) {
            int r = (w << 1) + rr;
            float m = -1e30f;
            for (int c = lane; c < 1024; c += 32) m = fmaxf(m, S[r * 1025 + c]);
            #pragma unroll
            for (int off = 16; off; off >>= 1) m = fmaxf(m, __shfl_xor_sync(0xffffffffu, m, off));
            float sum = 0.f;
            for (int c = lane; c < 1024; c += 32) {
                float p = __expf(S[r * 1025 + c] - m);
                S[r * 1025 + c] = p; sum += p;
            }
            #pragma unroll
            for (int off = 16; off; off >>= 1) sum += __shfl_xor_sync(0xffffffffu, sum, off);
            if (lane == 0) rowinv[r] = 1.f / sum;
        }
    }
    __syncthreads();
    {
        int kb = t >> 2, part = t & 3;
        float acc = 0.f;
        #pragma unroll
        for (int i = 0; i < 4; i++) {
            int r = (part << 2) + i;
            float s = 0.f;
            #pragma unroll
            for (int j = 0; j < 16; j++) s += S[r * 1025 + (kb << 4) + j];
            acc += s * rowinv[r];
        }
        ppart[t] = acc;
    }
    __syncthreads();
    if (t < 64)
        pooled[t] = ppart[t * 4] + ppart[t * 4 + 1] + ppart[t * 4 + 2] + ppart[t * 4 + 3];
    __syncthreads();
    if (t == 0) { float tot = 0.f; for (int i = 0; i < 64; i++) tot += pooled[i]; total_s = tot; }
    __syncthreads();
    if (t < 64) {
        float mine = pooled[t], before = 0.f;
        for (int j = 0; j < 64; j++) {
            float pj = pooled[j];
            if (pj > mine || (pj == mine && j < t)) before += pj;
        }
        keepflag[t] = (before < 0.5f * total_s) ? 1 : 0;
    }
    __syncthreads();
    if (t == 0) {
        unsigned long long bits = 0ull;
        for (int b = 0; b < 64; b++) if (keepflag[b]) bits |= (1ull << b);
        g_keep_bits[h][qb] = bits;
    }
}

// ---------------------------------------------------------------------------
// Kernel 2: block-sparse attention, mma.sync on pre-split bf16, cp.async
// double-buffered K/V. Grid (64,8), 128 threads.
// Smem map (bf16 idx, tile=4608): Qhi=0 Qlo=4608 |
//   st0: kh=9216 kl=13824 vh=18432 vl=23040 | st1: kh=0 kl=4608 vh=27648 vl=32256
// Stage-1 reuses the Q region only after Q fragments are register-resident.
// ---------------------------------------------------------------------------
#define TS 72

__global__ __launch_bounds__(128) void attn_hmma_kernel(float* __restrict__ out)
{
    const int qb = blockIdx.x, h = blockIdx.y;
    const int t = threadIdx.x, w = t >> 5, lane = t & 31;

    extern __shared__ __nv_bfloat16 sm[];
    __shared__ int ulist[64];
    __shared__ int ucnt_s;

    const uint32_t b0 = smem_u32(sm);
    const uint32_t qhiB = b0, qloB = b0 + 4608u * 2;
    const uint32_t khB[2] = { b0 + 9216u * 2,  b0 };
    const uint32_t klB[2] = { b0 + 13824u * 2, b0 + 4608u * 2 };
    const uint32_t vhB[2] = { b0 + 18432u * 2, b0 + 27648u * 2 };
    const uint32_t vlB[2] = { b0 + 23040u * 2, b0 + 32256u * 2 };

    if (t == 0) {
        unsigned long long u = g_keep_bits[h][qb];
        int c = 0;
        for (int b = 0; b < 64; b++) if ((u >> b) & 1ull) ulist[c++] = b;
        ucnt_s = c;
    }

    // Async-load Q hi/lo tiles. Thread: row t>>1, 64B half-row (t&1).
    const int r2 = t >> 1, half = t & 1;
    const uint32_t rowoff = (uint32_t)(r2 * 144 + half * 64);
    {
        const int gq = ((((h << 12) + (qb << 6) + r2) << 6) + half * 32);
        #pragma unroll
        for (int c = 0; c < 4; c++) cp16(qhiB + rowoff + c * 16, gQhi + gq + c * 8);
        #pragma unroll
        for (int c = 0; c < 4; c++) cp16(qloB + rowoff + c * 16, gQlo + gq + c * 8);
    }
    CP_COMMIT();
    asm volatile("cp.async.wait_group 0;" ::: "memory");
    __syncthreads();
    const int ucnt = ucnt_s;

    // Prefetch stage 0 (block ulist[0]) — does not touch the Q region.
    {
        const int kb = ulist[0];
        const int g = ((((h << 12) + (kb << 6) + r2) << 6) + half * 32);
        #pragma unroll
        for (int c = 0; c < 4; c++) {
            cp16(khB[0] + rowoff + c * 16, gKhi + g + c * 8);
            cp16(klB[0] + rowoff + c * 16, gKlo + g + c * 8);
            cp16(vhB[0] + rowoff + c * 16, gVhi + g + c * 8);
            cp16(vlB[0] + rowoff + c * 16, gVlo + g + c * 8);
        }
    }
    CP_COMMIT();

    // Q fragments (persistent).
    const int m0 = w * 16;
    uint32_t qfh[4][4], qfl[4][4];
    {
        const int mat = lane >> 3, mr = lane & 7;
        const int arow = m0 + ((mat & 1) << 3) + mr;
        const int acol0 = (mat >> 1) << 3;
        #pragma unroll
        for (int ks = 0; ks < 4; ks++) {
            ldm_x4(qfh[ks], qhiB + (uint32_t)(arow * TS + 16 * ks + acol0) * 2);
            ldm_x4(qfl[ks], qloB + (uint32_t)(arow * TS + 16 * ks + acol0) * 2);
        }
    }
    __syncthreads();   // all Q fragments extracted before stage1 prefetch overwrites

    float oAcc[8][4] = {};
    float lsum0 = 0.f, lsum1 = 0.f;
    const int g8 = (lane >> 3) << 3;
    const int lr = lane & 7;

    for (int it = 0; it < ucnt; it++) {
        const int cur = it & 1;
        if (it + 1 < ucnt) {
            const int kb = ulist[it + 1];
            const int nxt = cur ^ 1;
            const int g = ((((h << 12) + (kb << 6) + r2) << 6) + half * 32);
            #pragma unroll
            for (int c = 0; c < 4; c++) {
                cp16(khB[nxt] + rowoff + c * 16, gKhi + g + c * 8);
                cp16(klB[nxt] + rowoff + c * 16, gKlo + g + c * 8);
                cp16(vhB[nxt] + rowoff + c * 16, gVhi + g + c * 8);
                cp16(vlB[nxt] + rowoff + c * 16, gVlo + g + c * 8);
            }
        }
        CP_COMMIT();
        CP_WAIT1();           // current stage landed
        __syncthreads();

        const uint32_t kh = khB[cur], kl = klB[cur], vh = vhB[cur], vl = vlB[cur];

        // ---- S = Q K^T (3-term split).
        float sC[8][4] = {};
        #pragma unroll
        for (int kk = 0; kk < 2; kk++) {
            #pragma unroll
            for (int nt = 0; nt < 8; nt++) {
                uint32_t baddr = (uint32_t)((8 * nt + lr) * TS + 32 * kk + g8) * 2;
                uint32_t bh[4], bl[4];
                ldm_x4(bh, kh + baddr);
                ldm_x4(bl, kl + baddr);
                mma16816(sC[nt], qfh[2 * kk],     bh[0], bh[1]);
                mma16816(sC[nt], qfh[2 * kk + 1], bh[2], bh[3]);
                mma16816(sC[nt], qfh[2 * kk],     bl[0], bl[1]);
                mma16816(sC[nt], qfh[2 * kk + 1], bl[2], bl[3]);
                mma16816(sC[nt], qfl[2 * kk],     bh[0], bh[1]);
                mma16816(sC[nt], qfl[2 * kk + 1], bh[2], bh[3]);
            }
        }

        // ---- exp, l accumulate, pack P fragments (registers only).
        uint32_t ph[8][2], pl[8][2];
        #pragma unroll
        for (int nt = 0; nt < 8; nt++) {
            float p0 = __expf(sC[nt][0]), p1 = __expf(sC[nt][1]);
            float p2 = __expf(sC[nt][2]), p3 = __expf(sC[nt][3]);
            lsum0 += p0 + p1; lsum1 += p2 + p3;
            split2(p0, p1, ph[nt][0], pl[nt][0]);
            split2(p2, p3, ph[nt][1], pl[nt][1]);
        }

        // ---- O += P V (3-term split).
        #pragma unroll
        for (int kk = 0; kk < 2; kk++) {
            uint32_t pa0[4] = { ph[4*kk][0], ph[4*kk][1], ph[4*kk+1][0], ph[4*kk+1][1] };
            uint32_t la0[4] = { pl[4*kk][0], pl[4*kk][1], pl[4*kk+1][0], pl[4*kk+1][1] };
            uint32_t pa1[4] = { ph[4*kk+2][0], ph[4*kk+2][1], ph[4*kk+3][0], ph[4*kk+3][1] };
            uint32_t la1[4] = { pl[4*kk+2][0], pl[4*kk+2][1], pl[4*kk+3][0], pl[4*kk+3][1] };
            #pragma unroll
            for (int nt = 0; nt < 8; nt++) {
                uint32_t baddr = (uint32_t)((32 * kk + g8 + lr) * TS + 8 * nt) * 2;
                uint32_t bh[4], bl[4];
                ldm_x4_t(bh, vh + baddr);
                ldm_x4_t(bl, vl + baddr);
                mma16816(oAcc[nt], pa0, bh[0], bh[1]);
                mma16816(oAcc[nt], pa1, bh[2], bh[3]);
                mma16816(oAcc[nt], pa0, bl[0], bl[1]);
                mma16816(oAcc[nt], pa1, bl[2], bl[3]);
                mma16816(oAcc[nt], la0, bh[0], bh[1]);
                mma16816(oAcc[nt], la1, bh[2], bh[3]);
            }
        }
        __syncthreads();  // compute done before next prefetch overwrites cur
    }

    #pragma unroll
    for (int off = 1; off < 4; off <<= 1) {
        lsum0 += __shfl_xor_sync(0xffffffffu, lsum0, off, 4);
        lsum1 += __shfl_xor_sync(0xffffffffu, lsum1, off, 4);
    }
    const float inv0 = 1.f / lsum0, inv1 = 1.f / lsum1;

    {
        const int r0 = (qb << 6) + m0 + (lane >> 2);
        const int cc = (lane & 3) << 1;
        float* o0 = out + (((h << 12) + r0) << 6) + cc;
        float* o1 = o0 + (8 << 6);
        #pragma unroll
        for (int nt = 0; nt < 8; nt++) {
            *(float2*)(o0 + 8 * nt) = make_float2(oAcc[nt][0] * inv0, oAcc[nt][1] * inv0);
            *(float2*)(o1 + 8 * nt) = make_float2(oAcc[nt][2] * inv1, oAcc[nt][3] * inv1);
        }
    }
}

extern "C" void kernel_launch(void* const* d_in, const int* in_sizes, int n_in,
                              void* d_out, int out_size) {
    const float* q  = (const float*)d_in[0];
    const float* k  = (const float*)d_in[1];
    const float* v  = (const float*)d_in[2];
    const int* siq  = (const int*)d_in[3];
    const int* sik  = (const int*)d_in[4];
    float* out = (float*)d_out;

    const int pool_smem = (256 * 65 + 16 * 1025) * (int)sizeof(float);  // 132160
    const int attn_smem = 73728;
    cudaFuncSetAttribute(pool_mask_kernel, cudaFuncAttributeMaxDynamicSharedMemorySize, pool_smem);
    cudaFuncSetAttribute(attn_hmma_kernel, cudaFuncAttributeMaxDynamicSharedMemorySize, attn_smem);

    split_prepass<<<1024, 256>>>(q, k, v);
    pool_mask_kernel<<<dim3(64, 8), 256, pool_smem>>>(q, k, siq, sik);
    attn_hmma_kernel<<<dim3(64, 8), 128, attn_smem>>>(out);
}

// round 7
// speedup vs baseline: 2.2195x; 1.1279x over previous
#include <cuda_runtime.h>
#include <cuda_bf16.h>
#include <cstdint>

#define NHEADS 8
#define NELEM 2097152   // 8*4096*64
__device__ unsigned long long g_keep_bits[NHEADS][64];
__device__ __align__(128) __nv_bfloat16 gQhi[NELEM], gQlo[NELEM];
__device__ __align__(128) __nv_bfloat16 gKhi[NELEM], gKlo[NELEM];
__device__ __align__(128) __nv_bfloat16 gVhi[NELEM], gVlo[NELEM];

// ---------------- helpers ----------------
__device__ __forceinline__ uint32_t smem_u32(const void* p) {
    uint32_t a;
    asm("{ .reg .u64 t; cvta.to.shared.u64 t, %1; cvt.u32.u64 %0, t; }" : "=r"(a) : "l"(p));
    return a;
}
__device__ __forceinline__ void ldm_x4(uint32_t* d, uint32_t addr) {
    asm volatile("ldmatrix.sync.aligned.m8n8.x4.shared.b16 {%0,%1,%2,%3}, [%4];"
                 : "=r"(d[0]), "=r"(d[1]), "=r"(d[2]), "=r"(d[3]) : "r"(addr));
}
__device__ __forceinline__ void ldm_x4_t(uint32_t* d, uint32_t addr) {
    asm volatile("ldmatrix.sync.aligned.m8n8.x4.trans.shared.b16 {%0,%1,%2,%3}, [%4];"
                 : "=r"(d[0]), "=r"(d[1]), "=r"(d[2]), "=r"(d[3]) : "r"(addr));
}
__device__ __forceinline__ void mma16816(float* c, const uint32_t* a, uint32_t b0, uint32_t b1) {
    asm volatile(
        "mma.sync.aligned.m16n8k16.row.col.f32.bf16.bf16.f32 "
        "{%0,%1,%2,%3}, {%4,%5,%6,%7}, {%8,%9}, {%0,%1,%2,%3};"
        : "+f"(c[0]), "+f"(c[1]), "+f"(c[2]), "+f"(c[3])
        : "r"(a[0]), "r"(a[1]), "r"(a[2]), "r"(a[3]), "r"(b0), "r"(b1));
}
__device__ __forceinline__ void split2(float a, float b, uint32_t& h, uint32_t& l) {
    __nv_bfloat16 ha = __float2bfloat16(a), hb = __float2bfloat16(b);
    __nv_bfloat16 la = __float2bfloat16(a - __bfloat162float(ha));
    __nv_bfloat16 lb = __float2bfloat16(b - __bfloat162float(hb));
    h = (uint32_t)__bfloat16_as_ushort(ha) | ((uint32_t)__bfloat16_as_ushort(hb) << 16);
    l = (uint32_t)__bfloat16_as_ushort(la) | ((uint32_t)__bfloat16_as_ushort(lb) << 16);
}
__device__ __forceinline__ void cp16(uint32_t dst, const void* src) {
    asm volatile("cp.async.cg.shared.global [%0], [%1], 16;" :: "r"(dst), "l"(src));
}
#define CP_COMMIT() asm volatile("cp.async.commit_group;" ::: "memory")

// ---------------------------------------------------------------------------
// Kernel 0: split Q (x1/8), K, V into hi/lo bf16 global arrays.
// ---------------------------------------------------------------------------
__global__ __launch_bounds__(256) void split_prepass(
    const float* __restrict__ q, const float* __restrict__ k, const float* __restrict__ v)
{
    const int idx = (blockIdx.x * 256 + threadIdx.x) * 8;
    float4 a, b; uint32_t hw[4], lw[4];

    a = *(const float4*)(q + idx); b = *(const float4*)(q + idx + 4);
    split2(a.x * 0.125f, a.y * 0.125f, hw[0], lw[0]);
    split2(a.z * 0.125f, a.w * 0.125f, hw[1], lw[1]);
    split2(b.x * 0.125f, b.y * 0.125f, hw[2], lw[2]);
    split2(b.z * 0.125f, b.w * 0.125f, hw[3], lw[3]);
    *(uint4*)(gQhi + idx) = make_uint4(hw[0], hw[1], hw[2], hw[3]);
    *(uint4*)(gQlo + idx) = make_uint4(lw[0], lw[1], lw[2], lw[3]);

    a = *(const float4*)(k + idx); b = *(const float4*)(k + idx + 4);
    split2(a.x, a.y, hw[0], lw[0]); split2(a.z, a.w, hw[1], lw[1]);
    split2(b.x, b.y, hw[2], lw[2]); split2(b.z, b.w, hw[3], lw[3]);
    *(uint4*)(gKhi + idx) = make_uint4(hw[0], hw[1], hw[2], hw[3]);
    *(uint4*)(gKlo + idx) = make_uint4(lw[0], lw[1], lw[2], lw[3]);

    a = *(const float4*)(v + idx); b = *(const float4*)(v + idx + 4);
    split2(a.x, a.y, hw[0], lw[0]); split2(a.z, a.w, hw[1], lw[1]);
    split2(b.x, b.y, hw[2], lw[2]); split2(b.z, b.w, hw[3], lw[3]);
    *(uint4*)(gVhi + idx) = make_uint4(hw[0], hw[1], hw[2], hw[3]);
    *(uint4*)(gVlo + idx) = make_uint4(lw[0], lw[1], lw[2], lw[3]);
}

// ---------------------------------------------------------------------------
// Kernel 1: pooled downsampled attention -> keep bitmap. (Unchanged, passing.)
// ---------------------------------------------------------------------------
__global__ __launch_bounds__(256, 1) void pool_mask_kernel(
    const float* __restrict__ q, const float* __restrict__ k,
    const int* __restrict__ sidq, const int* __restrict__ sidk)
{
    const int qb = blockIdx.x, h = blockIdx.y;
    const int t = threadIdx.x;
    extern __shared__ float dynp[];
    float* SK = dynp;
    float* S  = dynp + 256 * 65;
    __shared__ float SQ[16 * 65];
    __shared__ int sqi[16], ski[16];
    __shared__ float rowinv[16];
    __shared__ float pooled[64];
    __shared__ float ppart[256];
    __shared__ int keepflag[64];
    __shared__ float total_s;

    if (t < 16) { sqi[t] = sidq[h * 16 + t]; ski[t] = sidk[h * 16 + t]; }
    __syncthreads();
    {
        int r = t >> 4, c4 = (t & 15) << 2;
        int grow = (qb << 6) + sqi[r];
        float4 val = *reinterpret_cast<const float4*>(q + ((((h << 12) + grow) << 6) + c4));
        SQ[r * 65 + c4 + 0] = val.x; SQ[r * 65 + c4 + 1] = val.y;
        SQ[r * 65 + c4 + 2] = val.z; SQ[r * 65 + c4 + 3] = val.w;
    }
    const int rt = t >> 6, ct = t & 63;
    for (int ck = 0; ck < 4; ck++) {
        __syncthreads();
        for (int i = t; i < 4096; i += 256) {
            int r = i >> 4, c4 = (i & 15) << 2;
            int kb = (ck << 4) + (r >> 4);
            int grow = (kb << 6) + ski[r & 15];
            float4 val = *reinterpret_cast<const float4*>(k + ((((h << 12) + grow) << 6) + c4));
            SK[r * 65 + c4 + 0] = val.x; SK[r * 65 + c4 + 1] = val.y;
            SK[r * 65 + c4 + 2] = val.z; SK[r * 65 + c4 + 3] = val.w;
        }
        __syncthreads();
        float sacc[4][4] = {};
        for (int d = 0; d < 64; d++) {
            float qv[4], kv[4];
            #pragma unroll
            for (int i = 0; i < 4; i++) qv[i] = SQ[((rt << 2) + i) * 65 + d];
            #pragma unroll
            for (int j = 0; j < 4; j++) kv[j] = SK[(ct + (j << 6)) * 65 + d];
            #pragma unroll
            for (int i = 0; i < 4; i++)
                #pragma unroll
                for (int j = 0; j < 4; j++) sacc[i][j] += qv[i] * kv[j];
        }
        #pragma unroll
        for (int i = 0; i < 4; i++)
            #pragma unroll
            for (int j = 0; j < 4; j++)
                S[((rt << 2) + i) * 1025 + (ck << 8) + ct + (j << 6)] = sacc[i][j] * 0.125f;
    }
    __syncthreads();
    {
        int w = t >> 5, lane = t & 31;
        for (int rr = 0; rr < 2; rr++) {
            int r = (w << 1) + rr;
            float m = -1e30f;
            for (int c = lane; c < 1024; c += 32) m = fmaxf(m, S[r * 1025 + c]);
            #pragma unroll
            for (int off = 16; off; off >>= 1) m = fmaxf(m, __shfl_xor_sync(0xffffffffu, m, off));
            float sum = 0.f;
            for (int c = lane; c < 1024; c += 32) {
                float p = __expf(S[r * 1025 + c] - m);
                S[r * 1025 + c] = p; sum += p;
            }
            #pragma unroll
            for (int off = 16; off; off >>= 1) sum += __shfl_xor_sync(0xffffffffu, sum, off);
            if (lane == 0) rowinv[r] = 1.f / sum;
        }
    }
    __syncthreads();
    {
        int kb = t >> 2, part = t & 3;
        float acc = 0.f;
        #pragma unroll
        for (int i = 0; i < 4; i++) {
            int r = (part << 2) + i;
            float s = 0.f;
            #pragma unroll
            for (int j = 0; j < 16; j++) s += S[r * 1025 + (kb << 4) + j];
            acc += s * rowinv[r];
        }
        ppart[t] = acc;
    }
    __syncthreads();
    if (t < 64)
        pooled[t] = ppart[t * 4] + ppart[t * 4 + 1] + ppart[t * 4 + 2] + ppart[t * 4 + 3];
    __syncthreads();
    if (t == 0) { float tot = 0.f; for (int i = 0; i < 64; i++) tot += pooled[i]; total_s = tot; }
    __syncthreads();
    if (t < 64) {
        float mine = pooled[t], before = 0.f;
        for (int j = 0; j < 64; j++) {
            float pj = pooled[j];
            if (pj > mine || (pj == mine && j < t)) before += pj;
        }
        keepflag[t] = (before < 0.5f * total_s) ? 1 : 0;
    }
    __syncthreads();
    if (t == 0) {
        unsigned long long bits = 0ull;
        for (int b = 0; b < 64; b++) if (keepflag[b]) bits |= (1ull << b);
        g_keep_bits[h][qb] = bits;
    }
}

// ---------------------------------------------------------------------------
// Kernel 2: block-sparse attention, mma.sync on pre-split bf16.
// K double-buffered (stage1 reuses Q region), V single-buffered.
// Smem (bf16 idx, tile=4608): Qhi=0 Qlo=4608 kh0=9216 kl0=13824
//   vh=18432 vl=23040 | kh1=0 kl1=4608.   Total 55296 B -> 4 CTAs/SM.
// Per iter: commit V(it); commit K(it+1); wait_group 2 (K(it) in) -> S;
//           wait_group 1 (V(it) in) -> PV.
// ---------------------------------------------------------------------------
#define TS 72

__global__ __launch_bounds__(128, 4) void attn_hmma_kernel(float* __restrict__ out)
{
    const int qb = blockIdx.x, h = blockIdx.y;
    const int t = threadIdx.x, w = t >> 5, lane = t & 31;

    extern __shared__ __nv_bfloat16 sm[];
    __shared__ int ulist[64];
    __shared__ int ucnt_s;

    const uint32_t b0 = smem_u32(sm);
    const uint32_t qhiB = b0, qloB = b0 + 4608u * 2;
    const uint32_t khB[2] = { b0 + 9216u * 2,  b0 };
    const uint32_t klB[2] = { b0 + 13824u * 2, b0 + 4608u * 2 };
    const uint32_t vhBa = b0 + 18432u * 2;
    const uint32_t vlBa = b0 + 23040u * 2;

    if (t == 0) {
        unsigned long long u = g_keep_bits[h][qb];
        int c = 0;
        for (int b = 0; b < 64; b++) if ((u >> b) & 1ull) ulist[c++] = b;
        ucnt_s = c;
    }

    // Async-load Q hi/lo tiles. Thread: row t>>1, 64B half-row (t&1).
    const int r2 = t >> 1, half = t & 1;
    const uint32_t rowoff = (uint32_t)(r2 * 144 + half * 64);
    {
        const int gq = ((((h << 12) + (qb << 6) + r2) << 6) + half * 32);
        #pragma unroll
        for (int c = 0; c < 4; c++) cp16(qhiB + rowoff + c * 16, gQhi + gq + c * 8);
        #pragma unroll
        for (int c = 0; c < 4; c++) cp16(qloB + rowoff + c * 16, gQlo + gq + c * 8);
    }
    CP_COMMIT();
    asm volatile("cp.async.wait_group 0;" ::: "memory");
    __syncthreads();
    const int ucnt = ucnt_s;

    // Prefetch K(0) into stage-0 buffers (not the Q region).
    {
        const int kb = ulist[0];
        const int g = ((((h << 12) + (kb << 6) + r2) << 6) + half * 32);
        #pragma unroll
        for (int c = 0; c < 4; c++) {
            cp16(khB[0] + rowoff + c * 16, gKhi + g + c * 8);
            cp16(klB[0] + rowoff + c * 16, gKlo + g + c * 8);
        }
    }
    CP_COMMIT();

    // Q fragments (persistent).
    const int m0 = w * 16;
    uint32_t qfh[4][4], qfl[4][4];
    {
        const int mat = lane >> 3, mr = lane & 7;
        const int arow = m0 + ((mat & 1) << 3) + mr;
        const int acol0 = (mat >> 1) << 3;
        #pragma unroll
        for (int ks = 0; ks < 4; ks++) {
            ldm_x4(qfh[ks], qhiB + (uint32_t)(arow * TS + 16 * ks + acol0) * 2);
            ldm_x4(qfl[ks], qloB + (uint32_t)(arow * TS + 16 * ks + acol0) * 2);
        }
    }
    __syncthreads();   // Q fragments extracted before K(1) prefetch overwrites Q region

    float oAcc[8][4] = {};
    float lsum0 = 0.f, lsum1 = 0.f;
    const int g8 = (lane >> 3) << 3;
    const int lr = lane & 7;

    for (int it = 0; it < ucnt; it++) {
        const int cur = it & 1;
        // V(it) loads (own group).
        {
            const int kb = ulist[it];
            const int g = ((((h << 12) + (kb << 6) + r2) << 6) + half * 32);
            #pragma unroll
            for (int c = 0; c < 4; c++) {
                cp16(vhBa + rowoff + c * 16, gVhi + g + c * 8);
                cp16(vlBa + rowoff + c * 16, gVlo + g + c * 8);
            }
        }
        CP_COMMIT();
        // K(it+1) loads (own group; empty group on last iter keeps counts aligned).
        if (it + 1 < ucnt) {
            const int kb = ulist[it + 1];
            const int g = ((((h << 12) + (kb << 6) + r2) << 6) + half * 32);
            #pragma unroll
            for (int c = 0; c < 4; c++) {
                cp16(khB[cur ^ 1] + rowoff + c * 16, gKhi + g + c * 8);
                cp16(klB[cur ^ 1] + rowoff + c * 16, gKlo + g + c * 8);
            }
        }
        CP_COMMIT();
        asm volatile("cp.async.wait_group 2;" ::: "memory");  // K(it) landed
        __syncthreads();

        const uint32_t kh = khB[cur], kl = klB[cur];

        // ---- S = Q K^T (3-term split).
        float sC[8][4] = {};
        #pragma unroll
        for (int kk = 0; kk < 2; kk++) {
            #pragma unroll
            for (int nt = 0; nt < 8; nt++) {
                uint32_t baddr = (uint32_t)((8 * nt + lr) * TS + 32 * kk + g8) * 2;
                uint32_t bh[4], bl[4];
                ldm_x4(bh, kh + baddr);
                ldm_x4(bl, kl + baddr);
                mma16816(sC[nt], qfh[2 * kk],     bh[0], bh[1]);
                mma16816(sC[nt], qfh[2 * kk + 1], bh[2], bh[3]);
                mma16816(sC[nt], qfh[2 * kk],     bl[0], bl[1]);
                mma16816(sC[nt], qfh[2 * kk + 1], bl[2], bl[3]);
                mma16816(sC[nt], qfl[2 * kk],     bh[0], bh[1]);
                mma16816(sC[nt], qfl[2 * kk + 1], bh[2], bh[3]);
            }
        }

        // ---- exp, l accumulate, pack P fragments (registers only).
        uint32_t ph[8][2], pl[8][2];
        #pragma unroll
        for (int nt = 0; nt < 8; nt++) {
            float p0 = __expf(sC[nt][0]), p1 = __expf(sC[nt][1]);
            float p2 = __expf(sC[nt][2]), p3 = __expf(sC[nt][3]);
            lsum0 += p0 + p1; lsum1 += p2 + p3;
            split2(p0, p1, ph[nt][0], pl[nt][0]);
            split2(p2, p3, ph[nt][1], pl[nt][1]);
        }

        asm volatile("cp.async.wait_group 1;" ::: "memory");  // V(it) landed
        __syncthreads();

        // ---- O += P V (3-term split).
        #pragma unroll
        for (int kk = 0; kk < 2; kk++) {
            uint32_t pa0[4] = { ph[4*kk][0], ph[4*kk][1], ph[4*kk+1][0], ph[4*kk+1][1] };
            uint32_t la0[4] = { pl[4*kk][0], pl[4*kk][1], pl[4*kk+1][0], pl[4*kk+1][1] };
            uint32_t pa1[4] = { ph[4*kk+2][0], ph[4*kk+2][1], ph[4*kk+3][0], ph[4*kk+3][1] };
            uint32_t la1[4] = { pl[4*kk+2][0], pl[4*kk+2][1], pl[4*kk+3][0], pl[4*kk+3][1] };
            #pragma unroll
            for (int nt = 0; nt < 8; nt++) {
                uint32_t baddr = (uint32_t)((32 * kk + g8 + lr) * TS + 8 * nt) * 2;
                uint32_t bh[4], bl[4];
                ldm_x4_t(bh, vhBa + baddr);
                ldm_x4_t(bl, vlBa + baddr);
                mma16816(oAcc[nt], pa0, bh[0], bh[1]);
                mma16816(oAcc[nt], pa1, bh[2], bh[3]);
                mma16816(oAcc[nt], pa0, bl[0], bl[1]);
                mma16816(oAcc[nt], pa1, bl[2], bl[3]);
                mma16816(oAcc[nt], la0, bh[0], bh[1]);
                mma16816(oAcc[nt], la1, bh[2], bh[3]);
            }
        }
        __syncthreads();  // V reads + K(cur) reads done before next iter overwrites
    }

    #pragma unroll
    for (int off = 1; off < 4; off <<= 1) {
        lsum0 += __shfl_xor_sync(0xffffffffu, lsum0, off, 4);
        lsum1 += __shfl_xor_sync(0xffffffffu, lsum1, off, 4);
    }
    const float inv0 = 1.f / lsum0, inv1 = 1.f / lsum1;

    {
        const int r0 = (qb << 6) + m0 + (lane >> 2);
        const int cc = (lane & 3) << 1;
        float* o0 = out + (((h << 12) + r0) << 6) + cc;
        float* o1 = o0 + (8 << 6);
        #pragma unroll
        for (int nt = 0; nt < 8; nt++) {
            *(float2*)(o0 + 8 * nt) = make_float2(oAcc[nt][0] * inv0, oAcc[nt][1] * inv0);
            *(float2*)(o1 + 8 * nt) = make_float2(oAcc[nt][2] * inv1, oAcc[nt][3] * inv1);
        }
    }
}

extern "C" void kernel_launch(void* const* d_in, const int* in_sizes, int n_in,
                              void* d_out, int out_size) {
    const float* q  = (const float*)d_in[0];
    const float* k  = (const float*)d_in[1];
    const float* v  = (const float*)d_in[2];
    const int* siq  = (const int*)d_in[3];
    const int* sik  = (const int*)d_in[4];
    float* out = (float*)d_out;

    const int pool_smem = (256 * 65 + 16 * 1025) * (int)sizeof(float);  // 132160
    const int attn_smem = 55296;
    cudaFuncSetAttribute(pool_mask_kernel, cudaFuncAttributeMaxDynamicSharedMemorySize, pool_smem);
    cudaFuncSetAttribute(attn_hmma_kernel, cudaFuncAttributeMaxDynamicSharedMemorySize, attn_smem);

    split_prepass<<<1024, 256>>>(q, k, v);
    pool_mask_kernel<<<dim3(64, 8), 256, pool_smem>>>(q, k, siq, sik);
    attn_hmma_kernel<<<dim3(64, 8), 128, attn_smem>>>(out);
}

// round 8
// speedup vs baseline: 2.8759x; 1.2957x over previous
#include <cuda_runtime.h>
#include <cuda_fp16.h>
#include <cstdint>

#define NHEADS 8
#define NELEM 2097152   // 8*4096*64
__device__ unsigned long long g_keep_bits[NHEADS][64];
__device__ __align__(128) __half gQh[NELEM];              // fp16(q/8)
__device__ __align__(128) __half gKh[NELEM], gKl[NELEM];  // fp16 hi/lo of k
__device__ __align__(128) __half gVh[NELEM];              // fp16(v)

// ---------------- helpers ----------------
__device__ __forceinline__ uint32_t smem_u32(const void* p) {
    uint32_t a;
    asm("{ .reg .u64 t; cvta.to.shared.u64 t, %1; cvt.u32.u64 %0, t; }" : "=r"(a) : "l"(p));
    return a;
}
__device__ __forceinline__ void ldm_x4(uint32_t* d, uint32_t addr) {
    asm volatile("ldmatrix.sync.aligned.m8n8.x4.shared.b16 {%0,%1,%2,%3}, [%4];"
                 : "=r"(d[0]), "=r"(d[1]), "=r"(d[2]), "=r"(d[3]) : "r"(addr));
}
__device__ __forceinline__ void ldm_x4_t(uint32_t* d, uint32_t addr) {
    asm volatile("ldmatrix.sync.aligned.m8n8.x4.trans.shared.b16 {%0,%1,%2,%3}, [%4];"
                 : "=r"(d[0]), "=r"(d[1]), "=r"(d[2]), "=r"(d[3]) : "r"(addr));
}
__device__ __forceinline__ void mma16816(float* c, const uint32_t* a, uint32_t b0, uint32_t b1) {
    asm volatile(
        "mma.sync.aligned.m16n8k16.row.col.f32.f16.f16.f32 "
        "{%0,%1,%2,%3}, {%4,%5,%6,%7}, {%8,%9}, {%0,%1,%2,%3};"
        : "+f"(c[0]), "+f"(c[1]), "+f"(c[2]), "+f"(c[3])
        : "r"(a[0]), "r"(a[1]), "r"(a[2]), "r"(a[3]), "r"(b0), "r"(b1));
}
__device__ __forceinline__ uint32_t pack2h(float a, float b) {
    __half2 hh = __floats2half2_rn(a, b);
    return *reinterpret_cast<uint32_t*>(&hh);
}
__device__ __forceinline__ void split2h(float a, float b, uint32_t& h, uint32_t& l) {
    __half ha = __float2half_rn(a), hb = __float2half_rn(b);
    __half la = __float2half_rn(a - __half2float(ha));
    __half lb = __float2half_rn(b - __half2float(hb));
    h = (uint32_t)__half_as_ushort(ha) | ((uint32_t)__half_as_ushort(hb) << 16);
    l = (uint32_t)__half_as_ushort(la) | ((uint32_t)__half_as_ushort(lb) << 16);
}
__device__ __forceinline__ void cp16(uint32_t dst, const void* src) {
    asm volatile("cp.async.cg.shared.global [%0], [%1], 16;" :: "r"(dst), "l"(src));
}
#define CP_COMMIT() asm volatile("cp.async.commit_group;" ::: "memory")

// ---------------------------------------------------------------------------
// Kernel 0: convert Q (x1/8, fp16), K (fp16 hi/lo), V (fp16) global arrays.
// ---------------------------------------------------------------------------
__global__ __launch_bounds__(256) void split_prepass(
    const float* __restrict__ q, const float* __restrict__ k, const float* __restrict__ v)
{
    const int idx = (blockIdx.x * 256 + threadIdx.x) * 8;
    float4 a, b;

    a = *(const float4*)(q + idx); b = *(const float4*)(q + idx + 4);
    *(uint4*)(gQh + idx) = make_uint4(
        pack2h(a.x * 0.125f, a.y * 0.125f), pack2h(a.z * 0.125f, a.w * 0.125f),
        pack2h(b.x * 0.125f, b.y * 0.125f), pack2h(b.z * 0.125f, b.w * 0.125f));

    a = *(const float4*)(k + idx); b = *(const float4*)(k + idx + 4);
    uint32_t hw[4], lw[4];
    split2h(a.x, a.y, hw[0], lw[0]); split2h(a.z, a.w, hw[1], lw[1]);
    split2h(b.x, b.y, hw[2], lw[2]); split2h(b.z, b.w, hw[3], lw[3]);
    *(uint4*)(gKh + idx) = make_uint4(hw[0], hw[1], hw[2], hw[3]);
    *(uint4*)(gKl + idx) = make_uint4(lw[0], lw[1], lw[2], lw[3]);

    a = *(const float4*)(v + idx); b = *(const float4*)(v + idx + 4);
    *(uint4*)(gVh + idx) = make_uint4(
        pack2h(a.x, a.y), pack2h(a.z, a.w), pack2h(b.x, b.y), pack2h(b.z, b.w));
}

// ---------------------------------------------------------------------------
// Kernel 1: pooled downsampled attention -> keep bitmap. (Unchanged, fp32.)
// ---------------------------------------------------------------------------
__global__ __launch_bounds__(256, 1) void pool_mask_kernel(
    const float* __restrict__ q, const float* __restrict__ k,
    const int* __restrict__ sidq, const int* __restrict__ sidk)
{
    const int qb = blockIdx.x, h = blockIdx.y;
    const int t = threadIdx.x;
    extern __shared__ float dynp[];
    float* SK = dynp;
    float* S  = dynp + 256 * 65;
    __shared__ float SQ[16 * 65];
    __shared__ int sqi[16], ski[16];
    __shared__ float rowinv[16];
    __shared__ float pooled[64];
    __shared__ float ppart[256];
    __shared__ int keepflag[64];
    __shared__ float total_s;

    if (t < 16) { sqi[t] = sidq[h * 16 + t]; ski[t] = sidk[h * 16 + t]; }
    __syncthreads();
    {
        int r = t >> 4, c4 = (t & 15) << 2;
        int grow = (qb << 6) + sqi[r];
        float4 val = *reinterpret_cast<const float4*>(q + ((((h << 12) + grow) << 6) + c4));
        SQ[r * 65 + c4 + 0] = val.x; SQ[r * 65 + c4 + 1] = val.y;
        SQ[r * 65 + c4 + 2] = val.z; SQ[r * 65 + c4 + 3] = val.w;
    }
    const int rt = t >> 6, ct = t & 63;
    for (int ck = 0; ck < 4; ck++) {
        __syncthreads();
        for (int i = t; i < 4096; i += 256) {
            int r = i >> 4, c4 = (i & 15) << 2;
            int kb = (ck << 4) + (r >> 4);
            int grow = (kb << 6) + ski[r & 15];
            float4 val = *reinterpret_cast<const float4*>(k + ((((h << 12) + grow) << 6) + c4));
            SK[r * 65 + c4 + 0] = val.x; SK[r * 65 + c4 + 1] = val.y;
            SK[r * 65 + c4 + 2] = val.z; SK[r * 65 + c4 + 3] = val.w;
        }
        __syncthreads();
        float sacc[4][4] = {};
        for (int d = 0; d < 64; d++) {
            float qv[4], kv[4];
            #pragma unroll
            for (int i = 0; i < 4; i++) qv[i] = SQ[((rt << 2) + i) * 65 + d];
            #pragma unroll
            for (int j = 0; j < 4; j++) kv[j] = SK[(ct + (j << 6)) * 65 + d];
            #pragma unroll
            for (int i = 0; i < 4; i++)
                #pragma unroll
                for (int j = 0; j < 4; j++) sacc[i][j] += qv[i] * kv[j];
        }
        #pragma unroll
        for (int i = 0; i < 4; i++)
            #pragma unroll
            for (int j = 0; j < 4; j++)
                S[((rt << 2) + i) * 1025 + (ck << 8) + ct + (j << 6)] = sacc[i][j] * 0.125f;
    }
    __syncthreads();
    {
        int w = t >> 5, lane = t & 31;
        for (int rr = 0; rr < 2; rr++) {
            int r = (w << 1) + rr;
            float m = -1e30f;
            for (int c = lane; c < 1024; c += 32) m = fmaxf(m, S[r * 1025 + c]);
            #pragma unroll
            for (int off = 16; off; off >>= 1) m = fmaxf(m, __shfl_xor_sync(0xffffffffu, m, off));
            float sum = 0.f;
            for (int c = lane; c < 1024; c += 32) {
                float p = __expf(S[r * 1025 + c] - m);
                S[r * 1025 + c] = p; sum += p;
            }
            #pragma unroll
            for (int off = 16; off; off >>= 1) sum += __shfl_xor_sync(0xffffffffu, sum, off);
            if (lane == 0) rowinv[r] = 1.f / sum;
        }
    }
    __syncthreads();
    {
        int kb = t >> 2, part = t & 3;
        float acc = 0.f;
        #pragma unroll
        for (int i = 0; i < 4; i++) {
            int r = (part << 2) + i;
            float s = 0.f;
            #pragma unroll
            for (int j = 0; j < 16; j++) s += S[r * 1025 + (kb << 4) + j];
            acc += s * rowinv[r];
        }
        ppart[t] = acc;
    }
    __syncthreads();
    if (t < 64)
        pooled[t] = ppart[t * 4] + ppart[t * 4 + 1] + ppart[t * 4 + 2] + ppart[t * 4 + 3];
    __syncthreads();
    if (t == 0) { float tot = 0.f; for (int i = 0; i < 64; i++) tot += pooled[i]; total_s = tot; }
    __syncthreads();
    if (t < 64) {
        float mine = pooled[t], before = 0.f;
        for (int j = 0; j < 64; j++) {
            float pj = pooled[j];
            if (pj > mine || (pj == mine && j < t)) before += pj;
        }
        keepflag[t] = (before < 0.5f * total_s) ? 1 : 0;
    }
    __syncthreads();
    if (t == 0) {
        unsigned long long bits = 0ull;
        for (int b = 0; b < 64; b++) if (keepflag[b]) bits |= (1ull << b);
        g_keep_bits[h][qb] = bits;
    }
}

// ---------------------------------------------------------------------------
// Kernel 2: block-sparse attention, fp16 mma.sync, 2-term splits.
// S = Qh·(Kh + Kl);  O += (Ph + Pl)·Vh.  K double-buffered, V single-buffered.
// Smem (bytes, tile=9216): Qh/kh1=0  kh0=9216  kl0=18432  vh=27648  kl1=36864.
// Total 46080 B -> 4 CTAs/SM.
// ---------------------------------------------------------------------------
#define TS 72

__global__ __launch_bounds__(128, 4) void attn_hmma_kernel(float* __restrict__ out)
{
    const int qb = blockIdx.x, h = blockIdx.y;
    const int t = threadIdx.x, w = t >> 5, lane = t & 31;

    extern __shared__ __half sm[];
    __shared__ int ulist[64];
    __shared__ int ucnt_s;

    const uint32_t b0 = smem_u32(sm);
    const uint32_t qhB = b0;
    const uint32_t khB[2] = { b0 + 9216u,  b0 };
    const uint32_t klB[2] = { b0 + 18432u, b0 + 36864u };
    const uint32_t vhBa = b0 + 27648u;

    if (t == 0) {
        unsigned long long u = g_keep_bits[h][qb];
        int c = 0;
        for (int b = 0; b < 64; b++) if ((u >> b) & 1ull) ulist[c++] = b;
        ucnt_s = c;
    }

    // Async-load Q tile. Thread: row t>>1, 64B half-row (t&1).
    const int r2 = t >> 1, half = t & 1;
    const uint32_t rowoff = (uint32_t)(r2 * 144 + half * 64);
    {
        const int gq = ((((h << 12) + (qb << 6) + r2) << 6) + half * 32);
        #pragma unroll
        for (int c = 0; c < 4; c++) cp16(qhB + rowoff + c * 16, gQh + gq + c * 8);
    }
    CP_COMMIT();
    asm volatile("cp.async.wait_group 0;" ::: "memory");
    __syncthreads();
    const int ucnt = ucnt_s;

    // Prefetch K(0) into stage-0 buffers (not the Q region).
    {
        const int kb = ulist[0];
        const int g = ((((h << 12) + (kb << 6) + r2) << 6) + half * 32);
        #pragma unroll
        for (int c = 0; c < 4; c++) {
            cp16(khB[0] + rowoff + c * 16, gKh + g + c * 8);
            cp16(klB[0] + rowoff + c * 16, gKl + g + c * 8);
        }
    }
    CP_COMMIT();

    // Q fragments (persistent).
    const int m0 = w * 16;
    uint32_t qf[4][4];
    {
        const int mat = lane >> 3, mr = lane & 7;
        const int arow = m0 + ((mat & 1) << 3) + mr;
        const int acol0 = (mat >> 1) << 3;
        #pragma unroll
        for (int ks = 0; ks < 4; ks++)
            ldm_x4(qf[ks], qhB + (uint32_t)(arow * TS + 16 * ks + acol0) * 2);
    }
    __syncthreads();   // Q fragments extracted before K(1) prefetch overwrites Q region

    float oAcc[8][4] = {};
    float lsum0 = 0.f, lsum1 = 0.f;
    const int g8 = (lane >> 3) << 3;
    const int lr = lane & 7;

    for (int it = 0; it < ucnt; it++) {
        const int cur = it & 1;
        // V(it) loads (own group).
        {
            const int kb = ulist[it];
            const int g = ((((h << 12) + (kb << 6) + r2) << 6) + half * 32);
            #pragma unroll
            for (int c = 0; c < 4; c++)
                cp16(vhBa + rowoff + c * 16, gVh + g + c * 8);
        }
        CP_COMMIT();
        // K(it+1) loads (own group; empty group on last iter keeps counts aligned).
        if (it + 1 < ucnt) {
            const int kb = ulist[it + 1];
            const int g = ((((h << 12) + (kb << 6) + r2) << 6) + half * 32);
            #pragma unroll
            for (int c = 0; c < 4; c++) {
                cp16(khB[cur ^ 1] + rowoff + c * 16, gKh + g + c * 8);
                cp16(klB[cur ^ 1] + rowoff + c * 16, gKl + g + c * 8);
            }
        }
        CP_COMMIT();
        asm volatile("cp.async.wait_group 2;" ::: "memory");  // K(it) landed
        __syncthreads();

        const uint32_t kh = khB[cur], kl = klB[cur];

        // ---- S = Qh Kh^T + Qh Kl^T.
        float sC[8][4] = {};
        #pragma unroll
        for (int kk = 0; kk < 2; kk++) {
            #pragma unroll
            for (int nt = 0; nt < 8; nt++) {
                uint32_t baddr = (uint32_t)((8 * nt + lr) * TS + 32 * kk + g8) * 2;
                uint32_t bh[4], bl[4];
                ldm_x4(bh, kh + baddr);
                ldm_x4(bl, kl + baddr);
                mma16816(sC[nt], qf[2 * kk],     bh[0], bh[1]);
                mma16816(sC[nt], qf[2 * kk + 1], bh[2], bh[3]);
                mma16816(sC[nt], qf[2 * kk],     bl[0], bl[1]);
                mma16816(sC[nt], qf[2 * kk + 1], bl[2], bl[3]);
            }
        }

        // ---- exp, l accumulate, pack P fragments (fp16 hi/lo, registers only).
        uint32_t ph[8][2], pl[8][2];
        #pragma unroll
        for (int nt = 0; nt < 8; nt++) {
            float p0 = __expf(sC[nt][0]), p1 = __expf(sC[nt][1]);
            float p2 = __expf(sC[nt][2]), p3 = __expf(sC[nt][3]);
            lsum0 += p0 + p1; lsum1 += p2 + p3;
            split2h(p0, p1, ph[nt][0], pl[nt][0]);
            split2h(p2, p3, ph[nt][1], pl[nt][1]);
        }

        asm volatile("cp.async.wait_group 1;" ::: "memory");  // V(it) landed
        __syncthreads();

        // ---- O += (Ph + Pl) Vh.
        #pragma unroll
        for (int kk = 0; kk < 2; kk++) {
            uint32_t pa0[4] = { ph[4*kk][0], ph[4*kk][1], ph[4*kk+1][0], ph[4*kk+1][1] };
            uint32_t la0[4] = { pl[4*kk][0], pl[4*kk][1], pl[4*kk+1][0], pl[4*kk+1][1] };
            uint32_t pa1[4] = { ph[4*kk+2][0], ph[4*kk+2][1], ph[4*kk+3][0], ph[4*kk+3][1] };
            uint32_t la1[4] = { pl[4*kk+2][0], pl[4*kk+2][1], pl[4*kk+3][0], pl[4*kk+3][1] };
            #pragma unroll
            for (int nt = 0; nt < 8; nt++) {
                uint32_t baddr = (uint32_t)((32 * kk + g8 + lr) * TS + 8 * nt) * 2;
                uint32_t bh[4];
                ldm_x4_t(bh, vhBa + baddr);
                mma16816(oAcc[nt], pa0, bh[0], bh[1]);
                mma16816(oAcc[nt], pa1, bh[2], bh[3]);
                mma16816(oAcc[nt], la0, bh[0], bh[1]);
                mma16816(oAcc[nt], la1, bh[2], bh[3]);
            }
        }
        __syncthreads();  // V + K(cur) reads done before next iter overwrites
    }

    #pragma unroll
    for (int off = 1; off < 4; off <<= 1) {
        lsum0 += __shfl_xor_sync(0xffffffffu, lsum0, off, 4);
        lsum1 += __shfl_xor_sync(0xffffffffu, lsum1, off, 4);
    }
    const float inv0 = 1.f / lsum0, inv1 = 1.f / lsum1;

    {
        const int r0 = (qb << 6) + m0 + (lane >> 2);
        const int cc = (lane & 3) << 1;
        float* o0 = out + (((h << 12) + r0) << 6) + cc;
        float* o1 = o0 + (8 << 6);
        #pragma unroll
        for (int nt = 0; nt < 8; nt++) {
            *(float2*)(o0 + 8 * nt) = make_float2(oAcc[nt][0] * inv0, oAcc[nt][1] * inv0);
            *(float2*)(o1 + 8 * nt) = make_float2(oAcc[nt][2] * inv1, oAcc[nt][3] * inv1);
        }
    }
}

extern "C" void kernel_launch(void* const* d_in, const int* in_sizes, int n_in,
                              void* d_out, int out_size) {
    const float* q  = (const float*)d_in[0];
    const float* k  = (const float*)d_in[1];
    const float* v  = (const float*)d_in[2];
    const int* siq  = (const int*)d_in[3];
    const int* sik  = (const int*)d_in[4];
    float* out = (float*)d_out;

    const int pool_smem = (256 * 65 + 16 * 1025) * (int)sizeof(float);  // 132160
    const int attn_smem = 46080;
    cudaFuncSetAttribute(pool_mask_kernel, cudaFuncAttributeMaxDynamicSharedMemorySize, pool_smem);
    cudaFuncSetAttribute(attn_hmma_kernel, cudaFuncAttributeMaxDynamicSharedMemorySize, attn_smem);

    split_prepass<<<1024, 256>>>(q, k, v);
    pool_mask_kernel<<<dim3(64, 8), 256, pool_smem>>>(q, k, siq, sik);
    attn_hmma_kernel<<<dim3(64, 8), 128, attn_smem>>>(out);
}

// round 9
// speedup vs baseline: 3.9328x; 1.3675x over previous
#include <cuda_runtime.h>
#include <cuda_fp16.h>
#include <cstdint>

#define NHEADS 8
#define NELEM 2097152   // 8*4096*64
__device__ unsigned long long g_keep_bits[NHEADS][64];
__device__ __align__(128) __half gQh[NELEM];   // fp16(q/8)
__device__ __align__(128) __half gKh[NELEM];   // fp16(k)
__device__ __align__(128) __half gVh[NELEM];   // fp16(v)

// ---------------- helpers ----------------
__device__ __forceinline__ uint32_t smem_u32(const void* p) {
    uint32_t a;
    asm("{ .reg .u64 t; cvta.to.shared.u64 t, %1; cvt.u32.u64 %0, t; }" : "=r"(a) : "l"(p));
    return a;
}
__device__ __forceinline__ void ldm_x4(uint32_t* d, uint32_t addr) {
    asm volatile("ldmatrix.sync.aligned.m8n8.x4.shared.b16 {%0,%1,%2,%3}, [%4];"
                 : "=r"(d[0]), "=r"(d[1]), "=r"(d[2]), "=r"(d[3]) : "r"(addr));
}
__device__ __forceinline__ void ldm_x4_t(uint32_t* d, uint32_t addr) {
    asm volatile("ldmatrix.sync.aligned.m8n8.x4.trans.shared.b16 {%0,%1,%2,%3}, [%4];"
                 : "=r"(d[0]), "=r"(d[1]), "=r"(d[2]), "=r"(d[3]) : "r"(addr));
}
__device__ __forceinline__ void mma16816(float* c, const uint32_t* a, uint32_t b0, uint32_t b1) {
    asm volatile(
        "mma.sync.aligned.m16n8k16.row.col.f32.f16.f16.f32 "
        "{%0,%1,%2,%3}, {%4,%5,%6,%7}, {%8,%9}, {%0,%1,%2,%3};"
        : "+f"(c[0]), "+f"(c[1]), "+f"(c[2]), "+f"(c[3])
        : "r"(a[0]), "r"(a[1]), "r"(a[2]), "r"(a[3]), "r"(b0), "r"(b1));
}
__device__ __forceinline__ uint32_t pack2h(float a, float b) {
    __half2 hh = __floats2half2_rn(a, b);
    return *reinterpret_cast<uint32_t*>(&hh);
}
__device__ __forceinline__ void cp16(uint32_t dst, const void* src) {
    asm volatile("cp.async.cg.shared.global [%0], [%1], 16;" :: "r"(dst), "l"(src));
}
#define CP_COMMIT() asm volatile("cp.async.commit_group;" ::: "memory")

// ---------------------------------------------------------------------------
// Kernel 0: convert Q (x1/8), K, V to fp16 global arrays.
// ---------------------------------------------------------------------------
__global__ __launch_bounds__(256) void split_prepass(
    const float* __restrict__ q, const float* __restrict__ k, const float* __restrict__ v)
{
    const int idx = (blockIdx.x * 256 + threadIdx.x) * 8;
    float4 a, b;

    a = *(const float4*)(q + idx); b = *(const float4*)(q + idx + 4);
    *(uint4*)(gQh + idx) = make_uint4(
        pack2h(a.x * 0.125f, a.y * 0.125f), pack2h(a.z * 0.125f, a.w * 0.125f),
        pack2h(b.x * 0.125f, b.y * 0.125f), pack2h(b.z * 0.125f, b.w * 0.125f));

    a = *(const float4*)(k + idx); b = *(const float4*)(k + idx + 4);
    *(uint4*)(gKh + idx) = make_uint4(
        pack2h(a.x, a.y), pack2h(a.z, a.w), pack2h(b.x, b.y), pack2h(b.z, b.w));

    a = *(const float4*)(v + idx); b = *(const float4*)(v + idx + 4);
    *(uint4*)(gVh + idx) = make_uint4(
        pack2h(a.x, a.y), pack2h(a.z, a.w), pack2h(b.x, b.y), pack2h(b.z, b.w));
}

// ---------------------------------------------------------------------------
// Kernel 1: pooled downsampled attention -> keep bitmap. (Unchanged, fp32.)
// ---------------------------------------------------------------------------
__global__ __launch_bounds__(256, 1) void pool_mask_kernel(
    const float* __restrict__ q, const float* __restrict__ k,
    const int* __restrict__ sidq, const int* __restrict__ sidk)
{
    const int qb = blockIdx.x, h = blockIdx.y;
    const int t = threadIdx.x;
    extern __shared__ float dynp[];
    float* SK = dynp;
    float* S  = dynp + 256 * 65;
    __shared__ float SQ[16 * 65];
    __shared__ int sqi[16], ski[16];
    __shared__ float rowinv[16];
    __shared__ float pooled[64];
    __shared__ float ppart[256];
    __shared__ int keepflag[64];
    __shared__ float total_s;

    if (t < 16) { sqi[t] = sidq[h * 16 + t]; ski[t] = sidk[h * 16 + t]; }
    __syncthreads();
    {
        int r = t >> 4, c4 = (t & 15) << 2;
        int grow = (qb << 6) + sqi[r];
        float4 val = *reinterpret_cast<const float4*>(q + ((((h << 12) + grow) << 6) + c4));
        SQ[r * 65 + c4 + 0] = val.x; SQ[r * 65 + c4 + 1] = val.y;
        SQ[r * 65 + c4 + 2] = val.z; SQ[r * 65 + c4 + 3] = val.w;
    }
    const int rt = t >> 6, ct = t & 63;
    for (int ck = 0; ck < 4; ck++) {
        __syncthreads();
        for (int i = t; i < 4096; i += 256) {
            int r = i >> 4, c4 = (i & 15) << 2;
            int kb = (ck << 4) + (r >> 4);
            int grow = (kb << 6) + ski[r & 15];
            float4 val = *reinterpret_cast<const float4*>(k + ((((h << 12) + grow) << 6) + c4));
            SK[r * 65 + c4 + 0] = val.x; SK[r * 65 + c4 + 1] = val.y;
            SK[r * 65 + c4 + 2] = val.z; SK[r * 65 + c4 + 3] = val.w;
        }
        __syncthreads();
        float sacc[4][4] = {};
        for (int d = 0; d < 64; d++) {
            float qv[4], kv[4];
            #pragma unroll
            for (int i = 0; i < 4; i++) qv[i] = SQ[((rt << 2) + i) * 65 + d];
            #pragma unroll
            for (int j = 0; j < 4; j++) kv[j] = SK[(ct + (j << 6)) * 65 + d];
            #pragma unroll
            for (int i = 0; i < 4; i++)
                #pragma unroll
                for (int j = 0; j < 4; j++) sacc[i][j] += qv[i] * kv[j];
        }
        #pragma unroll
        for (int i = 0; i < 4; i++)
            #pragma unroll
            for (int j = 0; j < 4; j++)
                S[((rt << 2) + i) * 1025 + (ck << 8) + ct + (j << 6)] = sacc[i][j] * 0.125f;
    }
    __syncthreads();
    {
        int w = t >> 5, lane = t & 31;
        for (int rr = 0; rr < 2; rr++) {
            int r = (w << 1) + rr;
            float m = -1e30f;
            for (int c = lane; c < 1024; c += 32) m = fmaxf(m, S[r * 1025 + c]);
            #pragma unroll
            for (int off = 16; off; off >>= 1) m = fmaxf(m, __shfl_xor_sync(0xffffffffu, m, off));
            float sum = 0.f;
            for (int c = lane; c < 1024; c += 32) {
                float p = __expf(S[r * 1025 + c] - m);
                S[r * 1025 + c] = p; sum += p;
            }
            #pragma unroll
            for (int off = 16; off; off >>= 1) sum += __shfl_xor_sync(0xffffffffu, sum, off);
            if (lane == 0) rowinv[r] = 1.f / sum;
        }
    }
    __syncthreads();
    {
        int kb = t >> 2, part = t & 3;
        float acc = 0.f;
        #pragma unroll
        for (int i = 0; i < 4; i++) {
            int r = (part << 2) + i;
            float s = 0.f;
            #pragma unroll
            for (int j = 0; j < 16; j++) s += S[r * 1025 + (kb << 4) + j];
            acc += s * rowinv[r];
        }
        ppart[t] = acc;
    }
    __syncthreads();
    if (t < 64)
        pooled[t] = ppart[t * 4] + ppart[t * 4 + 1] + ppart[t * 4 + 2] + ppart[t * 4 + 3];
    __syncthreads();
    if (t == 0) { float tot = 0.f; for (int i = 0; i < 64; i++) tot += pooled[i]; total_s = tot; }
    __syncthreads();
    if (t < 64) {
        float mine = pooled[t], before = 0.f;
        for (int j = 0; j < 64; j++) {
            float pj = pooled[j];
            if (pj > mine || (pj == mine && j < t)) before += pj;
        }
        keepflag[t] = (before < 0.5f * total_s) ? 1 : 0;
    }
    __syncthreads();
    if (t == 0) {
        unsigned long long bits = 0ull;
        for (int b = 0; b < 64; b++) if (keepflag[b]) bits |= (1ull << b);
        g_keep_bits[h][qb] = bits;
    }
}

// ---------------------------------------------------------------------------
// Kernel 2: block-sparse attention, single-term fp16 mma.sync.
// S = Qh Kh^T;  O += Ph Vh.  K double-buffered (stage1 reuses Q region),
// V single-buffered.
// Smem (bytes, tile=9216): Qh/kh1=0  kh0=9216  vh=18432.  Total 27648 B.
// ---------------------------------------------------------------------------
#define TS 72

__global__ __launch_bounds__(128, 4) void attn_hmma_kernel(float* __restrict__ out)
{
    const int qb = blockIdx.x, h = blockIdx.y;
    const int t = threadIdx.x, w = t >> 5, lane = t & 31;

    extern __shared__ __half sm[];
    __shared__ int ulist[64];
    __shared__ int ucnt_s;

    const uint32_t b0 = smem_u32(sm);
    const uint32_t qhB = b0;
    const uint32_t khB[2] = { b0 + 9216u, b0 };
    const uint32_t vhBa = b0 + 18432u;

    if (t == 0) {
        unsigned long long u = g_keep_bits[h][qb];
        int c = 0;
        for (int b = 0; b < 64; b++) if ((u >> b) & 1ull) ulist[c++] = b;
        ucnt_s = c;
    }

    // Async-load Q tile. Thread: row t>>1, 64B half-row (t&1).
    const int r2 = t >> 1, half = t & 1;
    const uint32_t rowoff = (uint32_t)(r2 * 144 + half * 64);
    {
        const int gq = ((((h << 12) + (qb << 6) + r2) << 6) + half * 32);
        #pragma unroll
        for (int c = 0; c < 4; c++) cp16(qhB + rowoff + c * 16, gQh + gq + c * 8);
    }
    CP_COMMIT();
    asm volatile("cp.async.wait_group 0;" ::: "memory");
    __syncthreads();
    const int ucnt = ucnt_s;

    // Prefetch K(0) into stage-0 buffer (not the Q region).
    {
        const int kb = ulist[0];
        const int g = ((((h << 12) + (kb << 6) + r2) << 6) + half * 32);
        #pragma unroll
        for (int c = 0; c < 4; c++)
            cp16(khB[0] + rowoff + c * 16, gKh + g + c * 8);
    }
    CP_COMMIT();

    // Q fragments (persistent).
    const int m0 = w * 16;
    uint32_t qf[4][4];
    {
        const int mat = lane >> 3, mr = lane & 7;
        const int arow = m0 + ((mat & 1) << 3) + mr;
        const int acol0 = (mat >> 1) << 3;
        #pragma unroll
        for (int ks = 0; ks < 4; ks++)
            ldm_x4(qf[ks], qhB + (uint32_t)(arow * TS + 16 * ks + acol0) * 2);
    }
    __syncthreads();   // Q fragments extracted before K(1) prefetch overwrites Q region

    float oAcc[8][4] = {};
    float lsum0 = 0.f, lsum1 = 0.f;
    const int g8 = (lane >> 3) << 3;
    const int lr = lane & 7;

    for (int it = 0; it < ucnt; it++) {
        const int cur = it & 1;
        // V(it) loads (own group).
        {
            const int kb = ulist[it];
            const int g = ((((h << 12) + (kb << 6) + r2) << 6) + half * 32);
            #pragma unroll
            for (int c = 0; c < 4; c++)
                cp16(vhBa + rowoff + c * 16, gVh + g + c * 8);
        }
        CP_COMMIT();
        // K(it+1) loads (own group; empty group on last iter keeps counts aligned).
        if (it + 1 < ucnt) {
            const int kb = ulist[it + 1];
            const int g = ((((h << 12) + (kb << 6) + r2) << 6) + half * 32);
            #pragma unroll
            for (int c = 0; c < 4; c++)
                cp16(khB[cur ^ 1] + rowoff + c * 16, gKh + g + c * 8);
        }
        CP_COMMIT();
        asm volatile("cp.async.wait_group 2;" ::: "memory");  // K(it) landed
        __syncthreads();

        const uint32_t kh = khB[cur];

        // ---- S = Qh Kh^T.
        float sC[8][4] = {};
        #pragma unroll
        for (int kk = 0; kk < 2; kk++) {
            #pragma unroll
            for (int nt = 0; nt < 8; nt++) {
                uint32_t baddr = (uint32_t)((8 * nt + lr) * TS + 32 * kk + g8) * 2;
                uint32_t bh[4];
                ldm_x4(bh, kh + baddr);
                mma16816(sC[nt], qf[2 * kk],     bh[0], bh[1]);
                mma16816(sC[nt], qf[2 * kk + 1], bh[2], bh[3]);
            }
        }

        // ---- exp, l accumulate, pack P fragments (single fp16, registers only).
        uint32_t ph[8][2];
        #pragma unroll
        for (int nt = 0; nt < 8; nt++) {
            float p0 = __expf(sC[nt][0]), p1 = __expf(sC[nt][1]);
            float p2 = __expf(sC[nt][2]), p3 = __expf(sC[nt][3]);
            lsum0 += p0 + p1; lsum1 += p2 + p3;
            ph[nt][0] = pack2h(p0, p1);
            ph[nt][1] = pack2h(p2, p3);
        }

        asm volatile("cp.async.wait_group 1;" ::: "memory");  // V(it) landed
        __syncthreads();

        // ---- O += Ph Vh.
        #pragma unroll
        for (int kk = 0; kk < 2; kk++) {
            uint32_t pa0[4] = { ph[4*kk][0], ph[4*kk][1], ph[4*kk+1][0], ph[4*kk+1][1] };
            uint32_t pa1[4] = { ph[4*kk+2][0], ph[4*kk+2][1], ph[4*kk+3][0], ph[4*kk+3][1] };
            #pragma unroll
            for (int nt = 0; nt < 8; nt++) {
                uint32_t baddr = (uint32_t)((32 * kk + g8 + lr) * TS + 8 * nt) * 2;
                uint32_t bh[4];
                ldm_x4_t(bh, vhBa + baddr);
                mma16816(oAcc[nt], pa0, bh[0], bh[1]);
                mma16816(oAcc[nt], pa1, bh[2], bh[3]);
            }
        }
        __syncthreads();  // V + K(cur) reads done before next iter overwrites
    }

    #pragma unroll
    for (int off = 1; off < 4; off <<= 1) {
        lsum0 += __shfl_xor_sync(0xffffffffu, lsum0, off, 4);
        lsum1 += __shfl_xor_sync(0xffffffffu, lsum1, off, 4);
    }
    const float inv0 = 1.f / lsum0, inv1 = 1.f / lsum1;

    {
        const int r0 = (qb << 6) + m0 + (lane >> 2);
        const int cc = (lane & 3) << 1;
        float* o0 = out + (((h << 12) + r0) << 6) + cc;
        float* o1 = o0 + (8 << 6);
        #pragma unroll
        for (int nt = 0; nt < 8; nt++) {
            *(float2*)(o0 + 8 * nt) = make_float2(oAcc[nt][0] * inv0, oAcc[nt][1] * inv0);
            *(float2*)(o1 + 8 * nt) = make_float2(oAcc[nt][2] * inv1, oAcc[nt][3] * inv1);
        }
    }
}

extern "C" void kernel_launch(void* const* d_in, const int* in_sizes, int n_in,
                              void* d_out, int out_size) {
    const float* q  = (const float*)d_in[0];
    const float* k  = (const float*)d_in[1];
    const float* v  = (const float*)d_in[2];
    const int* siq  = (const int*)d_in[3];
    const int* sik  = (const int*)d_in[4];
    float* out = (float*)d_out;

    const int pool_smem = (256 * 65 + 16 * 1025) * (int)sizeof(float);  // 132160
    const int attn_smem = 27648;
    cudaFuncSetAttribute(pool_mask_kernel, cudaFuncAttributeMaxDynamicSharedMemorySize, pool_smem);
    cudaFuncSetAttribute(attn_hmma_kernel, cudaFuncAttributeMaxDynamicSharedMemorySize, attn_smem);

    split_prepass<<<1024, 256>>>(q, k, v);
    pool_mask_kernel<<<dim3(64, 8), 256, pool_smem>>>(q, k, siq, sik);
    attn_hmma_kernel<<<dim3(64, 8), 128, attn_smem>>>(out);
}

// round 10
// speedup vs baseline: 5.0601x; 1.2867x over previous
#include <cuda_runtime.h>
#include <cuda_fp16.h>
#include <cstdint>

#define NHEADS 8
#define NELEM 2097152   // 8*4096*64
__device__ unsigned long long g_keep_bits[NHEADS][64];
__device__ float g_pooled[NHEADS][64][64];
__device__ __align__(128) __half gQh[NELEM], gQl[NELEM];   // fp16 hi/lo of q/8
__device__ __align__(128) __half gKh[NELEM], gKl[NELEM];   // fp16 hi/lo of k
__device__ __align__(128) __half gVh[NELEM];               // fp16(v)

// ---------------- helpers ----------------
__device__ __forceinline__ uint32_t smem_u32(const void* p) {
    uint32_t a;
    asm("{ .reg .u64 t; cvta.to.shared.u64 t, %1; cvt.u32.u64 %0, t; }" : "=r"(a) : "l"(p));
    return a;
}
__device__ __forceinline__ void ldm_x4(uint32_t* d, uint32_t addr) {
    asm volatile("ldmatrix.sync.aligned.m8n8.x4.shared.b16 {%0,%1,%2,%3}, [%4];"
                 : "=r"(d[0]), "=r"(d[1]), "=r"(d[2]), "=r"(d[3]) : "r"(addr));
}
__device__ __forceinline__ void ldm_x4_t(uint32_t* d, uint32_t addr) {
    asm volatile("ldmatrix.sync.aligned.m8n8.x4.trans.shared.b16 {%0,%1,%2,%3}, [%4];"
                 : "=r"(d[0]), "=r"(d[1]), "=r"(d[2]), "=r"(d[3]) : "r"(addr));
}
__device__ __forceinline__ void mma16816(float* c, const uint32_t* a, uint32_t b0, uint32_t b1) {
    asm volatile(
        "mma.sync.aligned.m16n8k16.row.col.f32.f16.f16.f32 "
        "{%0,%1,%2,%3}, {%4,%5,%6,%7}, {%8,%9}, {%0,%1,%2,%3};"
        : "+f"(c[0]), "+f"(c[1]), "+f"(c[2]), "+f"(c[3])
        : "r"(a[0]), "r"(a[1]), "r"(a[2]), "r"(a[3]), "r"(b0), "r"(b1));
}
__device__ __forceinline__ uint32_t pack2h(float a, float b) {
    __half2 hh = __floats2half2_rn(a, b);
    return *reinterpret_cast<uint32_t*>(&hh);
}
__device__ __forceinline__ void split2h(float a, float b, uint32_t& h, uint32_t& l) {
    __half ha = __float2half_rn(a), hb = __float2half_rn(b);
    __half la = __float2half_rn(a - __half2float(ha));
    __half lb = __float2half_rn(b - __half2float(hb));
    h = (uint32_t)__half_as_ushort(ha) | ((uint32_t)__half_as_ushort(hb) << 16);
    l = (uint32_t)__half_as_ushort(la) | ((uint32_t)__half_as_ushort(lb) << 16);
}
__device__ __forceinline__ void cp16(uint32_t dst, const void* src) {
    asm volatile("cp.async.cg.shared.global [%0], [%1], 16;" :: "r"(dst), "l"(src));
}
#define CP_COMMIT() asm volatile("cp.async.commit_group;" ::: "memory")

// ---------------------------------------------------------------------------
// Kernel 0: convert Q (x1/8, hi/lo), K (hi/lo), V (fp16) global arrays.
// ---------------------------------------------------------------------------
__global__ __launch_bounds__(256) void split_prepass(
    const float* __restrict__ q, const float* __restrict__ k, const float* __restrict__ v)
{
    const int idx = (blockIdx.x * 256 + threadIdx.x) * 8;
    float4 a, b; uint32_t hw[4], lw[4];

    a = *(const float4*)(q + idx); b = *(const float4*)(q + idx + 4);
    split2h(a.x * 0.125f, a.y * 0.125f, hw[0], lw[0]);
    split2h(a.z * 0.125f, a.w * 0.125f, hw[1], lw[1]);
    split2h(b.x * 0.125f, b.y * 0.125f, hw[2], lw[2]);
    split2h(b.z * 0.125f, b.w * 0.125f, hw[3], lw[3]);
    *(uint4*)(gQh + idx) = make_uint4(hw[0], hw[1], hw[2], hw[3]);
    *(uint4*)(gQl + idx) = make_uint4(lw[0], lw[1], lw[2], lw[3]);

    a = *(const float4*)(k + idx); b = *(const float4*)(k + idx + 4);
    split2h(a.x, a.y, hw[0], lw[0]); split2h(a.z, a.w, hw[1], lw[1]);
    split2h(b.x, b.y, hw[2], lw[2]); split2h(b.z, b.w, hw[3], lw[3]);
    *(uint4*)(gKh + idx) = make_uint4(hw[0], hw[1], hw[2], hw[3]);
    *(uint4*)(gKl + idx) = make_uint4(lw[0], lw[1], lw[2], lw[3]);

    a = *(const float4*)(v + idx); b = *(const float4*)(v + idx + 4);
    *(uint4*)(gVh + idx) = make_uint4(
        pack2h(a.x, a.y), pack2h(a.z, a.w), pack2h(b.x, b.y), pack2h(b.z, b.w));
}

// ---------------------------------------------------------------------------
// Kernel 1a: pooled sampled attention via HMMA (3-term split, ranking-exact).
// Grid (16 qtiles, 8 heads), 128 threads. CTA: 64 sampled-q rows x 1024 k-samples
// in 16 column-tiles of 64.  E[r][kb] accumulated by MMA with a {0,1} selector B.
// Smem: SQh 0, SQl 9216, skh{18432,36864}, skl{27648,46080}. Total 55296 B.
// ---------------------------------------------------------------------------
#define TS 72

__global__ __launch_bounds__(128) void pool_gemm_kernel(
    const int* __restrict__ sidq, const int* __restrict__ sidk)
{
    const int qt = blockIdx.x, h = blockIdx.y;
    const int t = threadIdx.x, w = t >> 5, lane = t & 31;

    extern __shared__ __half sm[];
    __shared__ int sqi[16], ski16[16];

    const uint32_t b0 = smem_u32(sm);
    const uint32_t SQh = b0, SQl = b0 + 9216u;
    const uint32_t skh[2] = { b0 + 18432u, b0 + 36864u };
    const uint32_t skl[2] = { b0 + 27648u, b0 + 46080u };

    if (t < 16) { sqi[t] = sidq[h * 16 + t]; ski16[t] = sidk[h * 16 + t]; }
    __syncthreads();

    const int r2 = t >> 1, half = t & 1;
    const uint32_t rowoff = (uint32_t)(r2 * 144 + half * 64);

    // Gather sampled Q rows (hi+lo): local row r2 -> qblock 4qt + r2/16, pos sqi[r2%16].
    {
        const int grow = ((qt << 2) + (r2 >> 4)) * 64 + sqi[r2 & 15];
        const int g = (((h << 12) + grow) << 6) + half * 32;
        #pragma unroll
        for (int c = 0; c < 4; c++) {
            cp16(SQh + rowoff + c * 16, gQh + g + c * 8);
            cp16(SQl + rowoff + c * 16, gQl + g + c * 8);
        }
    }
    CP_COMMIT();
    // Gather K tile 0.
    {
        const int grow = (r2 >> 4) * 64 + ski16[r2 & 15];
        const int g = (((h << 12) + grow) << 6) + half * 32;
        #pragma unroll
        for (int c = 0; c < 4; c++) {
            cp16(skh[0] + rowoff + c * 16, gKh + g + c * 8);
            cp16(skl[0] + rowoff + c * 16, gKl + g + c * 8);
        }
    }
    CP_COMMIT();
    asm volatile("cp.async.wait_group 1;" ::: "memory");  // Q landed
    __syncthreads();

    // Q fragments (hi+lo, persistent).
    const int m0 = w * 16;
    uint32_t qfh[4][4], qfl[4][4];
    {
        const int mat = lane >> 3, mr = lane & 7;
        const int arow = m0 + ((mat & 1) << 3) + mr;
        const int acol0 = (mat >> 1) << 3;
        #pragma unroll
        for (int ks = 0; ks < 4; ks++) {
            ldm_x4(qfh[ks], SQh + (uint32_t)(arow * TS + 16 * ks + acol0) * 2);
            ldm_x4(qfl[ks], SQl + (uint32_t)(arow * TS + 16 * ks + acol0) * 2);
        }
    }

    float Ef[8][4] = {};
    float lsum0 = 0.f, lsum1 = 0.f;
    const int g8 = (lane >> 3) << 3;
    const int lr = lane & 7;
    const int myn = lane >> 2;   // selector B column owned by this lane

    for (int it = 0; it < 16; it++) {
        const int cur = it & 1;
        if (it + 1 < 16) {
            const int grow = (((it + 1) << 2) + (r2 >> 4)) * 64 + ski16[r2 & 15];
            const int g = (((h << 12) + grow) << 6) + half * 32;
            #pragma unroll
            for (int c = 0; c < 4; c++) {
                cp16(skh[cur ^ 1] + rowoff + c * 16, gKh + g + c * 8);
                cp16(skl[cur ^ 1] + rowoff + c * 16, gKl + g + c * 8);
            }
        }
        CP_COMMIT();
        asm volatile("cp.async.wait_group 1;" ::: "memory");  // K(it) landed
        __syncthreads();

        const uint32_t kh = skh[cur], kl = skl[cur];

        // ---- S = Qh Kh + Qh Kl + Ql Kh  (3-term, ranking-exact).
        float sC[8][4] = {};
        #pragma unroll
        for (int kk = 0; kk < 2; kk++) {
            #pragma unroll
            for (int nt = 0; nt < 8; nt++) {
                uint32_t baddr = (uint32_t)((8 * nt + lr) * TS + 32 * kk + g8) * 2;
                uint32_t bh[4], bl[4];
                ldm_x4(bh, kh + baddr);
                ldm_x4(bl, kl + baddr);
                mma16816(sC[nt], qfh[2 * kk],     bh[0], bh[1]);
                mma16816(sC[nt], qfh[2 * kk + 1], bh[2], bh[3]);
                mma16816(sC[nt], qfh[2 * kk],     bl[0], bl[1]);
                mma16816(sC[nt], qfh[2 * kk + 1], bl[2], bl[3]);
                mma16816(sC[nt], qfl[2 * kk],     bh[0], bh[1]);
                mma16816(sC[nt], qfl[2 * kk + 1], bh[2], bh[3]);
            }
        }

        // ---- exp, l accumulate, pack P hi/lo.
        uint32_t ph[8][2], pl[8][2];
        #pragma unroll
        for (int nt = 0; nt < 8; nt++) {
            float p0 = __expf(sC[nt][0]), p1 = __expf(sC[nt][1]);
            float p2 = __expf(sC[nt][2]), p3 = __expf(sC[nt][3]);
            lsum0 += p0 + p1; lsum1 += p2 + p3;
            split2h(p0, p1, ph[nt][0], pl[nt][0]);
            split2h(p2, p3, ph[nt][1], pl[nt][1]);
        }

        // ---- E += (Ph+Pl) * G, G = k-block indicator (exact, B in {0,1}).
        // k-chunk kk16 covers cols 16kk16..16kk16+15 = one k-block; its global kb
        // = 4it + kk16 -> E n-tile it>>1, position 4(it&1)+kk16.
        const int tgt_base = (it & 1) << 2;
        float* Edst = Ef[it >> 1];
        #pragma unroll
        for (int kk16 = 0; kk16 < 4; kk16++) {
            uint32_t sel = (myn == tgt_base + kk16) ? 0x3C003C00u : 0u;
            uint32_t pA[4] = { ph[2*kk16][0], ph[2*kk16][1], ph[2*kk16+1][0], ph[2*kk16+1][1] };
            uint32_t lA[4] = { pl[2*kk16][0], pl[2*kk16][1], pl[2*kk16+1][0], pl[2*kk16+1][1] };
            mma16816(Edst, pA, sel, sel);
            mma16816(Edst, lA, sel, sel);
        }
        __syncthreads();  // K(cur) reads done before next prefetch overwrites
    }

    // Row sums -> 1/l; reduce E/l over the warp's 16 rows.
    #pragma unroll
    for (int off = 1; off < 4; off <<= 1) {
        lsum0 += __shfl_xor_sync(0xffffffffu, lsum0, off, 4);
        lsum1 += __shfl_xor_sync(0xffffffffu, lsum1, off, 4);
    }
    const float inv0 = 1.f / lsum0, inv1 = 1.f / lsum1;
    const int qbout = (qt << 2) + w;
    #pragma unroll
    for (int t8 = 0; t8 < 8; t8++) {
        float v0 = Ef[t8][0] * inv0 + Ef[t8][2] * inv1;
        float v1 = Ef[t8][1] * inv0 + Ef[t8][3] * inv1;
        #pragma unroll
        for (int off = 4; off < 32; off <<= 1) {
            v0 += __shfl_xor_sync(0xffffffffu, v0, off);
            v1 += __shfl_xor_sync(0xffffffffu, v1, off);
        }
        if (lane < 4) {
            const int kb = 8 * t8 + 2 * lane;
            g_pooled[h][qbout][kb]     = v0;
            g_pooled[h][qbout][kb + 1] = v1;
        }
    }
}

// ---------------------------------------------------------------------------
// Kernel 1b: rank pooled mass per (h,qb) -> keep bitmap. Grid (64,8), 64 thr.
// ---------------------------------------------------------------------------
__global__ __launch_bounds__(64) void rank_kernel()
{
    const int qb = blockIdx.x, h = blockIdx.y, t = threadIdx.x;
    __shared__ float pv[64];
    __shared__ int kf[64];
    __shared__ float tot;

    pv[t] = g_pooled[h][qb][t];
    __syncthreads();
    if (t == 0) { float s = 0.f; for (int i = 0; i < 64; i++) s += pv[i]; tot = s; }
    __syncthreads();
    float mine = pv[t], before = 0.f;
    for (int j = 0; j < 64; j++) {
        float pj = pv[j];
        if (pj > mine || (pj == mine && j < t)) before += pj;
    }
    kf[t] = (before < 0.5f * tot) ? 1 : 0;
    __syncthreads();
    if (t == 0) {
        unsigned long long bits = 0ull;
        for (int b = 0; b < 64; b++) if (kf[b]) bits |= (1ull << b);
        g_keep_bits[h][qb] = bits;
    }
}

// ---------------------------------------------------------------------------
// Kernel 2: block-sparse attention, single-term fp16 mma.sync. (Unchanged R9.)
// ---------------------------------------------------------------------------
__global__ __launch_bounds__(128, 4) void attn_hmma_kernel(float* __restrict__ out)
{
    const int qb = blockIdx.x, h = blockIdx.y;
    const int t = threadIdx.x, w = t >> 5, lane = t & 31;

    extern __shared__ __half sm[];
    __shared__ int ulist[64];
    __shared__ int ucnt_s;

    const uint32_t b0 = smem_u32(sm);
    const uint32_t qhB = b0;
    const uint32_t khB[2] = { b0 + 9216u, b0 };
    const uint32_t vhBa = b0 + 18432u;

    if (t == 0) {
        unsigned long long u = g_keep_bits[h][qb];
        int c = 0;
        for (int b = 0; b < 64; b++) if ((u >> b) & 1ull) ulist[c++] = b;
        ucnt_s = c;
    }

    const int r2 = t >> 1, half = t & 1;
    const uint32_t rowoff = (uint32_t)(r2 * 144 + half * 64);
    {
        const int gq = ((((h << 12) + (qb << 6) + r2) << 6) + half * 32);
        #pragma unroll
        for (int c = 0; c < 4; c++) cp16(qhB + rowoff + c * 16, gQh + gq + c * 8);
    }
    CP_COMMIT();
    asm volatile("cp.async.wait_group 0;" ::: "memory");
    __syncthreads();
    const int ucnt = ucnt_s;

    {
        const int kb = ulist[0];
        const int g = ((((h << 12) + (kb << 6) + r2) << 6) + half * 32);
        #pragma unroll
        for (int c = 0; c < 4; c++)
            cp16(khB[0] + rowoff + c * 16, gKh + g + c * 8);
    }
    CP_COMMIT();

    const int m0 = w * 16;
    uint32_t qf[4][4];
    {
        const int mat = lane >> 3, mr = lane & 7;
        const int arow = m0 + ((mat & 1) << 3) + mr;
        const int acol0 = (mat >> 1) << 3;
        #pragma unroll
        for (int ks = 0; ks < 4; ks++)
            ldm_x4(qf[ks], qhB + (uint32_t)(arow * TS + 16 * ks + acol0) * 2);
    }
    __syncthreads();

    float oAcc[8][4] = {};
    float lsum0 = 0.f, lsum1 = 0.f;
    const int g8 = (lane >> 3) << 3;
    const int lr = lane & 7;

    for (int it = 0; it < ucnt; it++) {
        const int cur = it & 1;
        {
            const int kb = ulist[it];
            const int g = ((((h << 12) + (kb << 6) + r2) << 6) + half * 32);
            #pragma unroll
            for (int c = 0; c < 4; c++)
                cp16(vhBa + rowoff + c * 16, gVh + g + c * 8);
        }
        CP_COMMIT();
        if (it + 1 < ucnt) {
            const int kb = ulist[it + 1];
            const int g = ((((h << 12) + (kb << 6) + r2) << 6) + half * 32);
            #pragma unroll
            for (int c = 0; c < 4; c++)
                cp16(khB[cur ^ 1] + rowoff + c * 16, gKh + g + c * 8);
        }
        CP_COMMIT();
        asm volatile("cp.async.wait_group 2;" ::: "memory");
        __syncthreads();

        const uint32_t kh = khB[cur];

        float sC[8][4] = {};
        #pragma unroll
        for (int kk = 0; kk < 2; kk++) {
            #pragma unroll
            for (int nt = 0; nt < 8; nt++) {
                uint32_t baddr = (uint32_t)((8 * nt + lr) * TS + 32 * kk + g8) * 2;
                uint32_t bh[4];
                ldm_x4(bh, kh + baddr);
                mma16816(sC[nt], qf[2 * kk],     bh[0], bh[1]);
                mma16816(sC[nt], qf[2 * kk + 1], bh[2], bh[3]);
            }
        }

        uint32_t ph[8][2];
        #pragma unroll
        for (int nt = 0; nt < 8; nt++) {
            float p0 = __expf(sC[nt][0]), p1 = __expf(sC[nt][1]);
            float p2 = __expf(sC[nt][2]), p3 = __expf(sC[nt][3]);
            lsum0 += p0 + p1; lsum1 += p2 + p3;
            ph[nt][0] = pack2h(p0, p1);
            ph[nt][1] = pack2h(p2, p3);
        }

        asm volatile("cp.async.wait_group 1;" ::: "memory");
        __syncthreads();

        #pragma unroll
        for (int kk = 0; kk < 2; kk++) {
            uint32_t pa0[4] = { ph[4*kk][0], ph[4*kk][1], ph[4*kk+1][0], ph[4*kk+1][1] };
            uint32_t pa1[4] = { ph[4*kk+2][0], ph[4*kk+2][1], ph[4*kk+3][0], ph[4*kk+3][1] };
            #pragma unroll
            for (int nt = 0; nt < 8; nt++) {
                uint32_t baddr = (uint32_t)((32 * kk + g8 + lr) * TS + 8 * nt) * 2;
                uint32_t bh[4];
                ldm_x4_t(bh, vhBa + baddr);
                mma16816(oAcc[nt], pa0, bh[0], bh[1]);
                mma16816(oAcc[nt], pa1, bh[2], bh[3]);
            }
        }
        __syncthreads();
    }

    #pragma unroll
    for (int off = 1; off < 4; off <<= 1) {
        lsum0 += __shfl_xor_sync(0xffffffffu, lsum0, off, 4);
        lsum1 += __shfl_xor_sync(0xffffffffu, lsum1, off, 4);
    }
    const float inv0 = 1.f / lsum0, inv1 = 1.f / lsum1;

    {
        const int r0 = (qb << 6) + m0 + (lane >> 2);
        const int cc = (lane & 3) << 1;
        float* o0 = out + (((h << 12) + r0) << 6) + cc;
        float* o1 = o0 + (8 << 6);
        #pragma unroll
        for (int nt = 0; nt < 8; nt++) {
            *(float2*)(o0 + 8 * nt) = make_float2(oAcc[nt][0] * inv0, oAcc[nt][1] * inv0);
            *(float2*)(o1 + 8 * nt) = make_float2(oAcc[nt][2] * inv1, oAcc[nt][3] * inv1);
        }
    }
}

extern "C" void kernel_launch(void* const* d_in, const int* in_sizes, int n_in,
                              void* d_out, int out_size) {
    const float* q  = (const float*)d_in[0];
    const float* k  = (const float*)d_in[1];
    const float* v  = (const float*)d_in[2];
    const int* siq  = (const int*)d_in[3];
    const int* sik  = (const int*)d_in[4];
    float* out = (float*)d_out;

    const int pool_smem = 55296;
    const int attn_smem = 27648;
    cudaFuncSetAttribute(pool_gemm_kernel, cudaFuncAttributeMaxDynamicSharedMemorySize, pool_smem);
    cudaFuncSetAttribute(attn_hmma_kernel, cudaFuncAttributeMaxDynamicSharedMemorySize, attn_smem);

    split_prepass<<<1024, 256>>>(q, k, v);
    pool_gemm_kernel<<<dim3(16, 8), 128, pool_smem>>>(siq, sik);
    rank_kernel<<<dim3(64, 8), 64>>>();
    attn_hmma_kernel<<<dim3(64, 8), 128, attn_smem>>>(out);
}